// round 2
// baseline (speedup 1.0000x reference)
#include <cuda_runtime.h>
#include <math.h>

// ---------------------------------------------------------------------------
// Swin block: B=32, H=W=56, C=192, NH=6, WS=7, N=49, NW=64/img, HD=32, DEPTH=2
// ---------------------------------------------------------------------------
#define TOKENS 100352           // 32*56*56
#define NWIN_TOT 2048           // 32*64 windows
#define QKV_ELEMS 19267584      // 2048*6*49*32  (== TOKENS*192)

__device__ float g_hw[TOKENS * 192];     // windowed/normed activations & attn out
__device__ float g_q[QKV_ELEMS];
__device__ float g_k[QKV_ELEMS];
__device__ float g_v[QKV_ELEMS];
__device__ float g_h2[TOKENS * 768];     // MLP hidden

// ---------------------------------------------------------------------------
// LayerNorm. windowed=1: destination index m is in window layout; gather the
// shifted source token, normalize, write to out[m]. windowed=0: identity map.
// 192 threads = 1 channel each.
// ---------------------------------------------------------------------------
__global__ void ln_kernel(const float* __restrict__ x, const float* __restrict__ gam,
                          const float* __restrict__ bet, float* __restrict__ out,
                          int windowed, int shift)
{
    __shared__ float ssum[6], ssq[6];
    int m = blockIdx.x;
    int tid = threadIdx.x;
    int src;
    if (windowed) {
        int win = m / 49, n = m - win * 49;
        int bimg = win >> 6, wslot = win & 63;
        int wh = wslot >> 3, wc = wslot & 7;
        int i = n / 7, j = n - i * 7;
        int sh = wh * 7 + i + shift; if (sh >= 56) sh -= 56;
        int sw = wc * 7 + j + shift; if (sw >= 56) sw -= 56;
        src = bimg * 3136 + sh * 56 + sw;
    } else {
        src = m;
    }
    float v = x[(size_t)src * 192 + tid];
    float s = v, q = v * v;
    #pragma unroll
    for (int o = 16; o; o >>= 1) {
        s += __shfl_xor_sync(0xffffffffu, s, o);
        q += __shfl_xor_sync(0xffffffffu, q, o);
    }
    int w = tid >> 5;
    if ((tid & 31) == 0) { ssum[w] = s; ssq[w] = q; }
    __syncthreads();
    if (tid == 0) {
        float ts = 0.f, tq = 0.f;
        #pragma unroll
        for (int k2 = 0; k2 < 6; k2++) { ts += ssum[k2]; tq += ssq[k2]; }
        ssum[0] = ts; ssq[0] = tq;
    }
    __syncthreads();
    float mean = ssum[0] * (1.f / 192.f);
    float var  = ssq[0] * (1.f / 192.f) - mean * mean;
    float rstd = rsqrtf(var + 1e-5f);
    out[(size_t)m * 192 + tid] = (v - mean) * rstd * gam[tid] + bet[tid];
}

// ---------------------------------------------------------------------------
// Register-blocked fp32 GEMM: out[M,N] = A[M,K] @ W[K,N] + bias, with fused
// epilogues:
//   EPI=0: QKV scatter  -> O0/O1/O2 = q/k/v in [win, head, n, d] layout
//   EPI=1: proj         -> window-reverse + unshift + residual add into O0
//   EPI=2: fc1          -> exact GELU, store to O0 (stride N)
//   EPI=3: fc2          -> residual add into O0 (stride N)
// BM=128, BN=64, BK=16, 128 threads, 8x8 microtile. M=100352, N%64==0, K%16==0.
// ---------------------------------------------------------------------------
template <int EPI>
__global__ __launch_bounds__(128)
void gemm_kernel(const float* __restrict__ A, const float* __restrict__ W,
                 const float* __restrict__ bias,
                 float* __restrict__ O0, float* __restrict__ O1, float* __restrict__ O2,
                 int K, int N, int shift)
{
    __shared__ float As[16][132];   // [k][m], padded: 132*4B row stride (16B aligned)
    __shared__ float Ws[16][64];    // [k][n]
    const int t  = threadIdx.x;
    const int tx = t & 7;           // 8 col-groups
    const int ty = t >> 3;          // 16 row-groups
    const int bm = blockIdx.y * 128;
    const int bn = blockIdx.x * 64;

    float acc[8][8];
    #pragma unroll
    for (int i = 0; i < 8; i++)
        #pragma unroll
        for (int j = 0; j < 8; j++) acc[i][j] = 0.f;

    for (int k0 = 0; k0 < K; k0 += 16) {
        #pragma unroll
        for (int it = 0; it < 4; it++) {           // A tile: 128x16 = 512 float4
            int idx = t + it * 128;
            int row = idx >> 2, q4 = idx & 3;
            float4 av = *(const float4*)(A + (size_t)(bm + row) * K + k0 + q4 * 4);
            As[q4 * 4 + 0][row] = av.x;
            As[q4 * 4 + 1][row] = av.y;
            As[q4 * 4 + 2][row] = av.z;
            As[q4 * 4 + 3][row] = av.w;
        }
        #pragma unroll
        for (int it = 0; it < 2; it++) {           // W tile: 16x64 = 256 float4
            int idx = t + it * 128;
            int r = idx >> 4, c4 = idx & 15;
            *(float4*)(&Ws[r][c4 * 4]) =
                *(const float4*)(W + (size_t)(k0 + r) * N + bn + c4 * 4);
        }
        __syncthreads();
        #pragma unroll
        for (int kk = 0; kk < 16; kk++) {
            float a[8], b[8];
            *(float4*)(a)     = *(const float4*)(&As[kk][ty * 8]);
            *(float4*)(a + 4) = *(const float4*)(&As[kk][ty * 8 + 4]);
            *(float4*)(b)     = *(const float4*)(&Ws[kk][tx * 8]);
            *(float4*)(b + 4) = *(const float4*)(&Ws[kk][tx * 8 + 4]);
            #pragma unroll
            for (int i = 0; i < 8; i++)
                #pragma unroll
                for (int j = 0; j < 8; j++) acc[i][j] += a[i] * b[j];
        }
        __syncthreads();
    }

    #pragma unroll
    for (int i = 0; i < 8; i++) {
        int m = bm + ty * 8 + i;
        int win = 0, n = 0;
        long dstTok = 0;
        if (EPI == 0 || EPI == 1) { win = m / 49; n = m - win * 49; }
        if (EPI == 1) {
            int bimg = win >> 6, wslot = win & 63;
            int wh = wslot >> 3, wc = wslot & 7;
            int ii = n / 7, jj = n - ii * 7;
            int dh = wh * 7 + ii + shift; if (dh >= 56) dh -= 56;
            int dw = wc * 7 + jj + shift; if (dw >= 56) dw -= 56;
            dstTok = (long)bimg * 3136 + dh * 56 + dw;
        }
        #pragma unroll
        for (int j = 0; j < 8; j++) {
            int c = bn + tx * 8 + j;
            float val = acc[i][j] + bias[c];
            if (EPI == 0) {
                int tsel = c / 192;
                int rem  = c - tsel * 192;
                int h = rem >> 5, d = rem & 31;
                float* dst = (tsel == 0) ? O0 : ((tsel == 1) ? O1 : O2);
                dst[(((size_t)win * 6 + h) * 49 + n) * 32 + d] = val;
            } else if (EPI == 1) {
                O0[(size_t)dstTok * 192 + c] += val;
            } else if (EPI == 2) {
                O0[(size_t)m * N + c] = 0.5f * val * (1.f + erff(val * 0.70710678118654752f));
            } else {
                O0[(size_t)m * N + c] += val;
            }
        }
    }
}

// ---------------------------------------------------------------------------
// Attention: one block per (window, head). q/k/v [49,32] in padded smem.
// Inline rel-pos bias + shift mask (region ids), softmax, PV, write head-
// concatenated output into g_hw layout [win*49, 192].
// ---------------------------------------------------------------------------
__global__ __launch_bounds__(256)
void attn_kernel(const float* __restrict__ q, const float* __restrict__ k,
                 const float* __restrict__ v, float* __restrict__ out,
                 const float* __restrict__ bt, int shift)
{
    __shared__ float qs[49][33], ks[49][33], vs[49][33];
    __shared__ float prow[8][56];
    __shared__ int   rid[49];

    int blk  = blockIdx.x;
    int win  = blk / 6;
    int h    = blk - win * 6;
    int t    = threadIdx.x;
    int warp = t >> 5, lane = t & 31;

    size_t base = ((size_t)win * 6 + h) * 49 * 32;
    for (int idx = t; idx < 49 * 32; idx += 256) {
        int r = idx >> 5, d = idx & 31;
        qs[r][d] = q[base + idx];
        ks[r][d] = k[base + idx];
        vs[r][d] = v[base + idx];
    }
    if (t < 49) {
        int wslot = win & 63;
        int wh = wslot >> 3, wc = wslot & 7;
        int i = t / 7, j = t - i * 7;
        int pr = wh * 7 + i, pc = wc * 7 + j;
        int r0 = (pr < 49) ? 0 : ((pr < 53) ? 1 : 2);
        int c0 = (pc < 49) ? 0 : ((pc < 53) ? 1 : 2);
        rid[t] = r0 * 3 + c0;
    }
    __syncthreads();

    const float scale = 0.17677669529663687f;  // 32^-0.5

    for (int r = warp; r < 49; r += 8) {
        int ri = r / 7, rj = r - ri * 7;
        int c0 = lane, c1 = lane + 32;
        float s0, s1 = -1e30f;
        {
            float acc = 0.f;
            #pragma unroll
            for (int d = 0; d < 32; d++) acc += qs[r][d] * ks[c0][d];
            int ci = c0 / 7, cj = c0 - ci * 7;
            int bidx = (ri - ci + 6) * 13 + (rj - cj + 6);
            acc = acc * scale + bt[bidx * 6 + h];
            if (shift && rid[r] != rid[c0]) acc -= 100.f;
            s0 = acc;
        }
        if (c1 < 49) {
            float acc = 0.f;
            #pragma unroll
            for (int d = 0; d < 32; d++) acc += qs[r][d] * ks[c1][d];
            int ci = c1 / 7, cj = c1 - ci * 7;
            int bidx = (ri - ci + 6) * 13 + (rj - cj + 6);
            acc = acc * scale + bt[bidx * 6 + h];
            if (shift && rid[r] != rid[c1]) acc -= 100.f;
            s1 = acc;
        }
        float mx = fmaxf(s0, s1);
        #pragma unroll
        for (int o = 16; o; o >>= 1) mx = fmaxf(mx, __shfl_xor_sync(0xffffffffu, mx, o));
        float e0 = expf(s0 - mx);
        float e1 = (c1 < 49) ? expf(s1 - mx) : 0.f;
        float sum = e0 + e1;
        #pragma unroll
        for (int o = 16; o; o >>= 1) sum += __shfl_xor_sync(0xffffffffu, sum, o);
        prow[warp][c0] = e0;
        if (c1 < 49) prow[warp][c1] = e1;
        float inv = 1.f / sum;
        __syncwarp();
        float o = 0.f;
        #pragma unroll
        for (int c = 0; c < 49; c++) o += prow[warp][c] * vs[c][lane];
        o *= inv;
        out[((size_t)win * 49 + r) * 192 + h * 32 + lane] = o;
        __syncwarp();
    }
}

// ---------------------------------------------------------------------------
// Host launcher. Residual stream lives in d_out.
// Input order: x, n1g, n1b, qkv_w, qkv_b, bias_table, proj_w, proj_b,
//              n2g, n2b, fc1_w, fc1_b, fc2_w, fc2_b  (each with DEPTH=2 lead)
// ---------------------------------------------------------------------------
extern "C" void kernel_launch(void* const* d_in, const int* in_sizes, int n_in,
                              void* d_out, int out_size)
{
    const float* x    = (const float*)d_in[0];
    const float* n1g  = (const float*)d_in[1];
    const float* n1b  = (const float*)d_in[2];
    const float* qkvw = (const float*)d_in[3];
    const float* qkvb = (const float*)d_in[4];
    const float* bt   = (const float*)d_in[5];
    const float* pw   = (const float*)d_in[6];
    const float* pb   = (const float*)d_in[7];
    const float* n2g  = (const float*)d_in[8];
    const float* n2b  = (const float*)d_in[9];
    const float* f1w  = (const float*)d_in[10];
    const float* f1b  = (const float*)d_in[11];
    const float* f2w  = (const float*)d_in[12];
    const float* f2b  = (const float*)d_in[13];
    float* xo = (float*)d_out;

    float *hw, *q, *k, *v, *h2;
    cudaGetSymbolAddress((void**)&hw, g_hw);
    cudaGetSymbolAddress((void**)&q,  g_q);
    cudaGetSymbolAddress((void**)&k,  g_k);
    cudaGetSymbolAddress((void**)&v,  g_v);
    cudaGetSymbolAddress((void**)&h2, g_h2);

    cudaMemcpyAsync(xo, x, (size_t)TOKENS * 192 * sizeof(float),
                    cudaMemcpyDeviceToDevice, 0);

    for (int L = 0; L < 2; L++) {
        int shift = (L & 1) ? 3 : 0;
        // LN1 + shift + window partition
        ln_kernel<<<TOKENS, 192>>>(xo, n1g + L * 192, n1b + L * 192, hw, 1, shift);
        // QKV GEMM (M=100352, K=192, N=576) + scatter
        gemm_kernel<0><<<dim3(9, 784), 128>>>(hw, qkvw + (size_t)L * 192 * 576,
                                              qkvb + L * 576, q, k, v, 192, 576, shift);
        // Attention per (window, head)
        attn_kernel<<<NWIN_TOT * 6, 256>>>(q, k, v, hw, bt + L * 169 * 6, shift);
        // Proj GEMM (K=192, N=192) + window reverse + residual
        gemm_kernel<1><<<dim3(3, 784), 128>>>(hw, pw + (size_t)L * 192 * 192,
                                              pb + L * 192, xo, 0, 0, 192, 192, shift);
        // LN2
        ln_kernel<<<TOKENS, 192>>>(xo, n2g + L * 192, n2b + L * 192, hw, 0, 0);
        // fc1 GEMM (K=192, N=768) + GELU
        gemm_kernel<2><<<dim3(12, 784), 128>>>(hw, f1w + (size_t)L * 192 * 768,
                                               f1b + L * 768, h2, 0, 0, 192, 768, 0);
        // fc2 GEMM (K=768, N=192) + residual
        gemm_kernel<3><<<dim3(3, 784), 128>>>(h2, f2w + (size_t)L * 768 * 192,
                                              f2b + L * 192, xo, 0, 0, 768, 192, 0);
    }
}

// round 8
// speedup vs baseline: 1.1080x; 1.1080x over previous
#include <cuda_runtime.h>
#include <stdint.h>
#include <math.h>

// ---------------------------------------------------------------------------
// Swin block: B=32, H=W=56, C=192, NH=6, WS=7, N=49, NW=64/img, HD=32, DEPTH=2
// GEMMs on mma.sync m16n8k8 tf32 (portable sm_80+ ISA; tcgen05 is unavailable
// because the harness targets plain sm_103). Everything else fp32.
// ---------------------------------------------------------------------------
#define TOKENS 100352           // 32*56*56
#define NWIN_TOT 2048           // 32*64 windows
#define QKV_ELEMS 19267584      // 2048*6*49*32  (== TOKENS*192)

__device__ float g_hw[TOKENS * 192];     // windowed/normed activations & attn out
__device__ float g_q[QKV_ELEMS];
__device__ float g_k[QKV_ELEMS];
__device__ float g_v[QKV_ELEMS];
__device__ float g_h2[TOKENS * 768];     // MLP hidden

__device__ __forceinline__ uint32_t f2tf32(float f) {
    uint32_t r; asm("cvt.rna.tf32.f32 %0, %1;" : "=r"(r) : "f"(f)); return r;
}

// ---------------------------------------------------------------------------
// tf32 mma.sync GEMM: out[M,N] = A[M,K] @ W[K,N] + bias, fused epilogues:
//   EPI=0: QKV scatter   EPI=1: proj + window-reverse + residual
//   EPI=2: fc1 + GELU    EPI=3: fc2 + residual
// BM=128, BN=64, BK=32. 256 threads = 8 warps (4 m x 2 n), warp tile 32x32.
// Operands staged in smem in m16n8k8 FRAGMENT ORDER so the mainloop issues
// only conflict-free LDS.128 / LDS.64.
// ---------------------------------------------------------------------------
template <int EPI>
__global__ __launch_bounds__(256)
void tc_gemm(const float* __restrict__ A, const float* __restrict__ W,
             const float* __restrict__ bias,
             float* __restrict__ O0, float* __restrict__ O1, float* __restrict__ O2,
             int K, int N, int shift)
{
    // Af[mtile(8)][kstep(4)][lane(32)][reg(4)]  = 16 KB
    // Bf[ntile(8)][kstep(4)][lane(32)][reg(2)]  =  8 KB
    __shared__ uint32_t Af[8 * 4 * 32 * 4];
    __shared__ uint32_t Bf[8 * 4 * 32 * 2];

    const int t    = threadIdx.x;
    const int lane = t & 31, warp = t >> 5;
    const int wm   = warp >> 1, wn = warp & 1;   // 4 x 2 warp grid
    const int bm   = blockIdx.y * 128;
    const int bn   = blockIdx.x * 64;

    float acc[2][4][4];
    #pragma unroll
    for (int i = 0; i < 2; i++)
        #pragma unroll
        for (int j = 0; j < 4; j++)
            #pragma unroll
            for (int e = 0; e < 4; e++) acc[i][j][e] = 0.f;

    for (int k0 = 0; k0 < K; k0 += 32) {
        // ---- A producer: 128x32 floats -> tf32 fragments -------------------
        #pragma unroll
        for (int it = 0; it < 4; it++) {
            int idx = t + it * 256;              // 0..1023 float4s
            int row = idx >> 3, q = idx & 7;
            float4 av = *(const float4*)(A + (size_t)(bm + row) * K + k0 + q * 4);
            float vv[4] = { av.x, av.y, av.z, av.w };
            int mtile = row >> 4, r = row & 15;
            #pragma unroll
            for (int e = 0; e < 4; e++) {
                int kk = q * 4 + e;
                int kstep = kk >> 3, c = kk & 7;
                int ln = (r & 7) * 4 + (c & 3);
                int rg = ((r >> 3) & 1) | ((c >> 2) << 1);
                Af[((mtile * 4 + kstep) * 32 + ln) * 4 + rg] = f2tf32(vv[e]);
            }
        }
        // ---- B producer: 32x64 floats (W[k][n]) -> tf32 fragments ----------
        #pragma unroll
        for (int it = 0; it < 2; it++) {
            int idx = t + it * 256;              // 0..511 float4s
            int kl = idx >> 4, n4 = idx & 15;
            float4 bv = *(const float4*)(W + (size_t)(k0 + kl) * N + bn + n4 * 4);
            float vv[4] = { bv.x, bv.y, bv.z, bv.w };
            int kstep = kl >> 3, ck = kl & 7;
            int rg = ck >> 2;
            #pragma unroll
            for (int e = 0; e < 4; e++) {
                int nl = n4 * 4 + e;
                int ntile = nl >> 3, cn = nl & 7;
                int ln = cn * 4 + (ck & 3);
                Bf[((ntile * 4 + kstep) * 32 + ln) * 2 + rg] = f2tf32(vv[e]);
            }
        }
        __syncthreads();

        // ---- mainloop: 4 k-steps of m16n8k8 --------------------------------
        #pragma unroll
        for (int ks = 0; ks < 4; ks++) {
            uint32_t a[2][4], b[4][2];
            #pragma unroll
            for (int i = 0; i < 2; i++) {
                int mt = wm * 2 + i;
                uint4 av = *(const uint4*)(&Af[((mt * 4 + ks) * 32 + lane) * 4]);
                a[i][0] = av.x; a[i][1] = av.y; a[i][2] = av.z; a[i][3] = av.w;
            }
            #pragma unroll
            for (int j = 0; j < 4; j++) {
                int nt = wn * 4 + j;
                uint2 bvv = *(const uint2*)(&Bf[((nt * 4 + ks) * 32 + lane) * 2]);
                b[j][0] = bvv.x; b[j][1] = bvv.y;
            }
            #pragma unroll
            for (int i = 0; i < 2; i++)
                #pragma unroll
                for (int j = 0; j < 4; j++)
                    asm volatile(
                        "mma.sync.aligned.m16n8k8.row.col.f32.tf32.tf32.f32 "
                        "{%0,%1,%2,%3}, {%4,%5,%6,%7}, {%8,%9}, {%0,%1,%2,%3};"
                        : "+f"(acc[i][j][0]), "+f"(acc[i][j][1]),
                          "+f"(acc[i][j][2]), "+f"(acc[i][j][3])
                        : "r"(a[i][0]), "r"(a[i][1]), "r"(a[i][2]), "r"(a[i][3]),
                          "r"(b[j][0]), "r"(b[j][1]));
        }
        __syncthreads();
    }

    // ---- epilogue: D fragment c0..c3 -> fused stores -----------------------
    #pragma unroll
    for (int i = 0; i < 2; i++) {
        #pragma unroll
        for (int half = 0; half < 2; half++) {
            int m = bm + wm * 32 + i * 16 + (lane >> 2) + half * 8;
            int win = 0, n = 0;
            long dstTok = 0;
            if (EPI == 0 || EPI == 1) { win = m / 49; n = m - win * 49; }
            if (EPI == 1) {
                int bimg = win >> 6, wslot = win & 63;
                int wh = wslot >> 3, wc = wslot & 7;
                int ii = n / 7, jj = n - ii * 7;
                int dh = wh * 7 + ii + shift; if (dh >= 56) dh -= 56;
                int dw = wc * 7 + jj + shift; if (dw >= 56) dw -= 56;
                dstTok = (long)bimg * 3136 + dh * 56 + dw;
            }
            #pragma unroll
            for (int j = 0; j < 4; j++) {
                #pragma unroll
                for (int e = 0; e < 2; e++) {
                    int c = bn + wn * 32 + j * 8 + (lane & 3) * 2 + e;
                    float val = acc[i][j][half * 2 + e] + bias[c];
                    if (EPI == 0) {
                        int tsel = c / 192;
                        int rem  = c - tsel * 192;
                        int h = rem >> 5, d = rem & 31;
                        float* dst = (tsel == 0) ? O0 : ((tsel == 1) ? O1 : O2);
                        dst[(((size_t)win * 6 + h) * 49 + n) * 32 + d] = val;
                    } else if (EPI == 1) {
                        O0[(size_t)dstTok * 192 + c] += val;
                    } else if (EPI == 2) {
                        O0[(size_t)m * N + c] =
                            0.5f * val * (1.f + erff(val * 0.70710678118654752f));
                    } else {
                        O0[(size_t)m * N + c] += val;
                    }
                }
            }
        }
    }
}

// ---------------------------------------------------------------------------
// LayerNorm (+ optional shift + window partition gather). 192 threads.
// ---------------------------------------------------------------------------
__global__ void ln_kernel(const float* __restrict__ x, const float* __restrict__ gam,
                          const float* __restrict__ bet, float* __restrict__ out,
                          int windowed, int shift)
{
    __shared__ float ssum[6], ssq[6];
    int m = blockIdx.x;
    int tid = threadIdx.x;
    int src;
    if (windowed) {
        int win = m / 49, n = m - win * 49;
        int bimg = win >> 6, wslot = win & 63;
        int wh = wslot >> 3, wc = wslot & 7;
        int i = n / 7, j = n - i * 7;
        int sh = wh * 7 + i + shift; if (sh >= 56) sh -= 56;
        int sw = wc * 7 + j + shift; if (sw >= 56) sw -= 56;
        src = bimg * 3136 + sh * 56 + sw;
    } else {
        src = m;
    }
    float v = x[(size_t)src * 192 + tid];
    float s = v, q = v * v;
    #pragma unroll
    for (int o = 16; o; o >>= 1) {
        s += __shfl_xor_sync(0xffffffffu, s, o);
        q += __shfl_xor_sync(0xffffffffu, q, o);
    }
    int w = tid >> 5;
    if ((tid & 31) == 0) { ssum[w] = s; ssq[w] = q; }
    __syncthreads();
    if (tid == 0) {
        float ts = 0.f, tq = 0.f;
        #pragma unroll
        for (int k2 = 0; k2 < 6; k2++) { ts += ssum[k2]; tq += ssq[k2]; }
        ssum[0] = ts; ssq[0] = tq;
    }
    __syncthreads();
    float mean = ssum[0] * (1.f / 192.f);
    float var  = ssq[0] * (1.f / 192.f) - mean * mean;
    float rstd = rsqrtf(var + 1e-5f);
    out[(size_t)m * 192 + tid] = (v - mean) * rstd * gam[tid] + bet[tid];
}

// ---------------------------------------------------------------------------
// Attention: one block per (window, head); fp32 in smem.
// ---------------------------------------------------------------------------
__global__ __launch_bounds__(256)
void attn_kernel(const float* __restrict__ q, const float* __restrict__ k,
                 const float* __restrict__ v, float* __restrict__ out,
                 const float* __restrict__ bt, int shift)
{
    __shared__ float qs[49][33], ks[49][33], vs[49][33];
    __shared__ float prow[8][56];
    __shared__ int   rid[49];

    int blk  = blockIdx.x;
    int win  = blk / 6;
    int h    = blk - win * 6;
    int t    = threadIdx.x;
    int warp = t >> 5, lane = t & 31;

    size_t base = ((size_t)win * 6 + h) * 49 * 32;
    for (int idx = t; idx < 49 * 32; idx += 256) {
        int r = idx >> 5, d = idx & 31;
        qs[r][d] = q[base + idx];
        ks[r][d] = k[base + idx];
        vs[r][d] = v[base + idx];
    }
    if (t < 49) {
        int wslot = win & 63;
        int wh = wslot >> 3, wc = wslot & 7;
        int i = t / 7, j = t - i * 7;
        int pr = wh * 7 + i, pc = wc * 7 + j;
        int r0 = (pr < 49) ? 0 : ((pr < 53) ? 1 : 2);
        int c0 = (pc < 49) ? 0 : ((pc < 53) ? 1 : 2);
        rid[t] = r0 * 3 + c0;
    }
    __syncthreads();

    const float scale = 0.17677669529663687f;  // 32^-0.5

    for (int r = warp; r < 49; r += 8) {
        int ri = r / 7, rj = r - ri * 7;
        int c0 = lane, c1 = lane + 32;
        float s0, s1 = -1e30f;
        {
            float acc = 0.f;
            #pragma unroll
            for (int d = 0; d < 32; d++) acc += qs[r][d] * ks[c0][d];
            int ci = c0 / 7, cj = c0 - ci * 7;
            int bidx = (ri - ci + 6) * 13 + (rj - cj + 6);
            acc = acc * scale + bt[bidx * 6 + h];
            if (shift && rid[r] != rid[c0]) acc -= 100.f;
            s0 = acc;
        }
        if (c1 < 49) {
            float acc = 0.f;
            #pragma unroll
            for (int d = 0; d < 32; d++) acc += qs[r][d] * ks[c1][d];
            int ci = c1 / 7, cj = c1 - ci * 7;
            int bidx = (ri - ci + 6) * 13 + (rj - cj + 6);
            acc = acc * scale + bt[bidx * 6 + h];
            if (shift && rid[r] != rid[c1]) acc -= 100.f;
            s1 = acc;
        }
        float mx = fmaxf(s0, s1);
        #pragma unroll
        for (int o = 16; o; o >>= 1) mx = fmaxf(mx, __shfl_xor_sync(0xffffffffu, mx, o));
        float e0 = expf(s0 - mx);
        float e1 = (c1 < 49) ? expf(s1 - mx) : 0.f;
        float sum = e0 + e1;
        #pragma unroll
        for (int o = 16; o; o >>= 1) sum += __shfl_xor_sync(0xffffffffu, sum, o);
        prow[warp][c0] = e0;
        if (c1 < 49) prow[warp][c1] = e1;
        float inv = 1.f / sum;
        __syncwarp();
        float o = 0.f;
        #pragma unroll
        for (int c = 0; c < 49; c++) o += prow[warp][c] * vs[c][lane];
        o *= inv;
        out[((size_t)win * 49 + r) * 192 + h * 32 + lane] = o;
        __syncwarp();
    }
}

// ---------------------------------------------------------------------------
extern "C" void kernel_launch(void* const* d_in, const int* in_sizes, int n_in,
                              void* d_out, int out_size)
{
    const float* x    = (const float*)d_in[0];
    const float* n1g  = (const float*)d_in[1];
    const float* n1b  = (const float*)d_in[2];
    const float* qkvw = (const float*)d_in[3];
    const float* qkvb = (const float*)d_in[4];
    const float* bt   = (const float*)d_in[5];
    const float* pw   = (const float*)d_in[6];
    const float* pb   = (const float*)d_in[7];
    const float* n2g  = (const float*)d_in[8];
    const float* n2b  = (const float*)d_in[9];
    const float* f1w  = (const float*)d_in[10];
    const float* f1b  = (const float*)d_in[11];
    const float* f2w  = (const float*)d_in[12];
    const float* f2b  = (const float*)d_in[13];
    float* xo = (float*)d_out;

    float *hw, *q, *k, *v, *h2;
    cudaGetSymbolAddress((void**)&hw, g_hw);
    cudaGetSymbolAddress((void**)&q,  g_q);
    cudaGetSymbolAddress((void**)&k,  g_k);
    cudaGetSymbolAddress((void**)&v,  g_v);
    cudaGetSymbolAddress((void**)&h2, g_h2);

    cudaMemcpyAsync(xo, x, (size_t)TOKENS * 192 * sizeof(float),
                    cudaMemcpyDeviceToDevice, 0);

    for (int L = 0; L < 2; L++) {
        int shift = (L & 1) ? 3 : 0;
        ln_kernel<<<TOKENS, 192>>>(xo, n1g + L * 192, n1b + L * 192, hw, 1, shift);
        tc_gemm<0><<<dim3(9, 784), 256>>>(hw, qkvw + (size_t)L * 192 * 576,
                                          qkvb + L * 576, q, k, v, 192, 576, shift);
        attn_kernel<<<NWIN_TOT * 6, 256>>>(q, k, v, hw, bt + L * 169 * 6, shift);
        tc_gemm<1><<<dim3(3, 784), 256>>>(hw, pw + (size_t)L * 192 * 192,
                                          pb + L * 192, xo, 0, 0, 192, 192, shift);
        ln_kernel<<<TOKENS, 192>>>(xo, n2g + L * 192, n2b + L * 192, hw, 0, 0);
        tc_gemm<2><<<dim3(12, 784), 256>>>(hw, f1w + (size_t)L * 192 * 768,
                                           f1b + L * 768, h2, 0, 0, 192, 768, 0);
        tc_gemm<3><<<dim3(3, 784), 256>>>(h2, f2w + (size_t)L * 768 * 192,
                                          f2b + L * 192, xo, 0, 0, 768, 192, 0);
    }
}

// round 10
// speedup vs baseline: 1.2753x; 1.1510x over previous
#include <cuda_runtime.h>
#include <stdint.h>
#include <math.h>

// ---------------------------------------------------------------------------
// Swin block: B=32, H=W=56, C=192, NH=6, WS=7, N=49, NW=64/img, HD=32, DEPTH=2
// GEMMs: mma.sync m16n8k8 tf32 + ldmatrix + cp.async double buffering.
// All GEMM inputs pre-rounded to tf32 at their producers (weights in the
// one-time transpose kernel), so the mainloop is pure ldmatrix+mma.
// ---------------------------------------------------------------------------
#define TOKENS 100352
#define NWIN_TOT 2048
#define QKV_ELEMS 19267584      // TOKENS*192

__device__ float g_hw[TOKENS * 192];
__device__ float g_q[QKV_ELEMS];
__device__ float g_k[QKV_ELEMS];
__device__ float g_v[QKV_ELEMS];
__device__ float g_h2[TOKENS * 768];
// transposed+tf32-rounded weights, per layer: qkvT[576*192] projT[192*192]
// fc1T[768*192] fc2T[192*768]; layer stride 442368
__device__ float g_wt[884736];

__device__ __forceinline__ float f2tf32f(float f) {
    uint32_t r; asm("cvt.rna.tf32.f32 %0, %1;" : "=r"(r) : "f"(f));
    return __uint_as_float(r);
}

#define CP_ASYNC16(smem, gptr) \
    asm volatile("cp.async.cg.shared.global [%0], [%1], 16;" :: "r"(smem), "l"(gptr))
#define CP_COMMIT() asm volatile("cp.async.commit_group;" ::: "memory")
#define CP_WAIT0()  asm volatile("cp.async.wait_group 0;" ::: "memory")
#define CP_WAIT1()  asm volatile("cp.async.wait_group 1;" ::: "memory")

#define LDSM4(r0,r1,r2,r3,addr) \
    asm volatile("ldmatrix.sync.aligned.m8n8.x4.shared.b16 {%0,%1,%2,%3}, [%4];" \
        : "=r"(r0),"=r"(r1),"=r"(r2),"=r"(r3) : "r"(addr))

// ---------------------------------------------------------------------------
// Weight transpose + tf32 round: Wt[n*K+k] = tf32(W[k*N+n])
// ---------------------------------------------------------------------------
__global__ void transpose_tf32(const float* __restrict__ W, float* __restrict__ Wt,
                               int K, int N)
{
    __shared__ float tile[32][33];
    int k0 = blockIdx.x * 32, n0 = blockIdx.y * 32;
    int tx = threadIdx.x, ty = threadIdx.y;
    #pragma unroll
    for (int r = ty; r < 32; r += 8)
        tile[r][tx] = W[(size_t)(k0 + r) * N + n0 + tx];
    __syncthreads();
    #pragma unroll
    for (int r = ty; r < 32; r += 8)
        Wt[(size_t)(n0 + r) * K + k0 + tx] = f2tf32f(tile[tx][r]);
}

// ---------------------------------------------------------------------------
// tf32 tensor GEMM, BM=128 BN=64 BK=32, 256 threads = 8 warps (4m x 2n),
// warp tile 32x32. Double-buffered cp.async; ldmatrix fragment loads.
// Epilogues: 0=QKV scatter, 1=proj+winrev+residual, 2=fc1+GELU, 3=fc2+residual
// ---------------------------------------------------------------------------
template <int EPI>
__global__ __launch_bounds__(256)
void tc_gemm(const float* __restrict__ A, const float* __restrict__ Wt,
             const float* __restrict__ bias,
             float* __restrict__ O0, float* __restrict__ O1, float* __restrict__ O2,
             int K, int N, int shift)
{
    // [2 stages][ A:128x32f (16KB) | B:64x32f (8KB) ] = 48KB exactly
    __shared__ __align__(128) float smem[2 * 6144];

    const int t    = threadIdx.x;
    const int lane = t & 31, warp = t >> 5;
    const int wm   = warp >> 1, wn = warp & 1;
    const int bm   = blockIdx.y * 128;
    const int bn   = blockIdx.x * 64;

    const uint32_t smb  = (uint32_t)__cvta_generic_to_shared(smem);
    const uint32_t xorv = (lane & 7) << 4;
    const int rowA = wm * 32 + (lane & 7) + ((lane >> 3) & 1) * 8;
    const uint32_t tA = ((lane >> 4) & 1) * 16;
    const int rowB = wn * 32 + (lane & 7);
    const uint32_t tB = (lane >> 3) * 16;

    float acc[2][4][4];
    #pragma unroll
    for (int i = 0; i < 2; i++)
        #pragma unroll
        for (int j = 0; j < 4; j++)
            #pragma unroll
            for (int e = 0; e < 4; e++) acc[i][j][e] = 0.f;

    auto issue_chunk = [&](int kc, int sel) {
        const int k0 = kc << 5;
        const uint32_t Ab = smb + sel * 24576;
        const uint32_t Bb = Ab + 16384;
        #pragma unroll
        for (int it = 0; it < 4; it++) {              // A: 1024 16B chunks
            int idx = t + it * 256;
            int row = idx >> 3, kq = idx & 7;
            uint32_t off = (uint32_t)(row * 128 + kq * 16) ^ ((row & 7) << 4);
            CP_ASYNC16(Ab + off, A + (size_t)(bm + row) * K + k0 + kq * 4);
        }
        #pragma unroll
        for (int it = 0; it < 2; it++) {              // B: 512 16B chunks
            int idx = t + it * 256;
            int n = idx >> 3, kq = idx & 7;
            uint32_t off = (uint32_t)(n * 128 + kq * 16) ^ ((n & 7) << 4);
            CP_ASYNC16(Bb + off, Wt + (size_t)(bn + n) * K + k0 + kq * 4);
        }
    };

    const int nch = K >> 5;
    issue_chunk(0, 0);
    CP_COMMIT();

    for (int kc = 0; kc < nch; kc++) {
        const int sel = kc & 1;
        if (kc + 1 < nch) {
            issue_chunk(kc + 1, sel ^ 1);
            CP_COMMIT();
            CP_WAIT1();
        } else {
            CP_WAIT0();
        }
        __syncthreads();

        const uint32_t Ab = smb + sel * 24576;
        const uint32_t Bb = Ab + 16384;

        #pragma unroll
        for (int ks2 = 0; ks2 < 2; ks2++) {
            uint32_t b[4][4];
            #pragma unroll
            for (int j = 0; j < 4; j++) {
                uint32_t addr = Bb + (((uint32_t)((rowB + j * 8) * 128) + ks2 * 64 + tB) ^ xorv);
                LDSM4(b[j][0], b[j][1], b[j][2], b[j][3], addr);
            }
            #pragma unroll
            for (int ki = 0; ki < 2; ki++) {
                const int ks = ks2 * 2 + ki;
                uint32_t a[2][4];
                #pragma unroll
                for (int i = 0; i < 2; i++) {
                    uint32_t addr = Ab + (((uint32_t)((rowA + i * 16) * 128) + ks * 32 + tA) ^ xorv);
                    LDSM4(a[i][0], a[i][1], a[i][2], a[i][3], addr);
                }
                #pragma unroll
                for (int i = 0; i < 2; i++)
                    #pragma unroll
                    for (int j = 0; j < 4; j++)
                        asm volatile(
                            "mma.sync.aligned.m16n8k8.row.col.f32.tf32.tf32.f32 "
                            "{%0,%1,%2,%3}, {%4,%5,%6,%7}, {%8,%9}, {%0,%1,%2,%3};"
                            : "+f"(acc[i][j][0]), "+f"(acc[i][j][1]),
                              "+f"(acc[i][j][2]), "+f"(acc[i][j][3])
                            : "r"(a[i][0]), "r"(a[i][1]), "r"(a[i][2]), "r"(a[i][3]),
                              "r"(b[j][ki * 2]), "r"(b[j][ki * 2 + 1]));
            }
        }
        __syncthreads();
    }

    // ---- epilogue ----------------------------------------------------------
    #pragma unroll
    for (int i = 0; i < 2; i++) {
        #pragma unroll
        for (int half = 0; half < 2; half++) {
            int m = bm + wm * 32 + i * 16 + (lane >> 2) + half * 8;
            int win = 0, n = 0;
            long dstTok = 0;
            if (EPI == 0 || EPI == 1) { win = m / 49; n = m - win * 49; }
            if (EPI == 1) {
                int bimg = win >> 6, wslot = win & 63;
                int wh = wslot >> 3, wc = wslot & 7;
                int ii = n / 7, jj = n - ii * 7;
                int dh = wh * 7 + ii + shift; if (dh >= 56) dh -= 56;
                int dw = wc * 7 + jj + shift; if (dw >= 56) dw -= 56;
                dstTok = (long)bimg * 3136 + dh * 56 + dw;
            }
            #pragma unroll
            for (int j = 0; j < 4; j++) {
                #pragma unroll
                for (int e = 0; e < 2; e++) {
                    int c = bn + wn * 32 + j * 8 + (lane & 3) * 2 + e;
                    float val = acc[i][j][half * 2 + e] + bias[c];
                    if (EPI == 0) {
                        int tsel = c / 192;
                        int rem  = c - tsel * 192;
                        int h = rem >> 5, d = rem & 31;
                        float* dst = (tsel == 0) ? O0 : ((tsel == 1) ? O1 : O2);
                        dst[(((size_t)win * 6 + h) * 49 + n) * 32 + d] = val;
                    } else if (EPI == 1) {
                        O0[(size_t)dstTok * 192 + c] += val;
                    } else if (EPI == 2) {
                        float g = 0.5f * val * (1.f + erff(val * 0.70710678118654752f));
                        O0[(size_t)m * N + c] = f2tf32f(g);   // fc2 A-input
                    } else {
                        O0[(size_t)m * N + c] += val;
                    }
                }
            }
        }
    }
}

// ---------------------------------------------------------------------------
// LayerNorm (+ optional shift + window partition gather). Output is a GEMM
// A-input -> round to tf32 here. 192 threads.
// ---------------------------------------------------------------------------
__global__ void ln_kernel(const float* __restrict__ x, const float* __restrict__ gam,
                          const float* __restrict__ bet, float* __restrict__ out,
                          int windowed, int shift)
{
    __shared__ float ssum[6], ssq[6];
    int m = blockIdx.x;
    int tid = threadIdx.x;
    int src;
    if (windowed) {
        int win = m / 49, n = m - win * 49;
        int bimg = win >> 6, wslot = win & 63;
        int wh = wslot >> 3, wc = wslot & 7;
        int i = n / 7, j = n - i * 7;
        int sh = wh * 7 + i + shift; if (sh >= 56) sh -= 56;
        int sw = wc * 7 + j + shift; if (sw >= 56) sw -= 56;
        src = bimg * 3136 + sh * 56 + sw;
    } else {
        src = m;
    }
    float v = x[(size_t)src * 192 + tid];
    float s = v, q = v * v;
    #pragma unroll
    for (int o = 16; o; o >>= 1) {
        s += __shfl_xor_sync(0xffffffffu, s, o);
        q += __shfl_xor_sync(0xffffffffu, q, o);
    }
    int w = tid >> 5;
    if ((tid & 31) == 0) { ssum[w] = s; ssq[w] = q; }
    __syncthreads();
    if (tid == 0) {
        float ts = 0.f, tq = 0.f;
        #pragma unroll
        for (int k2 = 0; k2 < 6; k2++) { ts += ssum[k2]; tq += ssq[k2]; }
        ssum[0] = ts; ssq[0] = tq;
    }
    __syncthreads();
    float mean = ssum[0] * (1.f / 192.f);
    float var  = ssq[0] * (1.f / 192.f) - mean * mean;
    float rstd = rsqrtf(var + 1e-5f);
    out[(size_t)m * 192 + tid] = f2tf32f((v - mean) * rstd * gam[tid] + bet[tid]);
}

// ---------------------------------------------------------------------------
// Attention: one block per (window, head). Output feeds proj GEMM -> round.
// ---------------------------------------------------------------------------
__global__ __launch_bounds__(256)
void attn_kernel(const float* __restrict__ q, const float* __restrict__ k,
                 const float* __restrict__ v, float* __restrict__ out,
                 const float* __restrict__ bt, int shift)
{
    __shared__ float qs[49][33], ks[49][33], vs[49][33];
    __shared__ float prow[8][56];
    __shared__ int   rid[49];

    int blk  = blockIdx.x;
    int win  = blk / 6;
    int h    = blk - win * 6;
    int t    = threadIdx.x;
    int warp = t >> 5, lane = t & 31;

    size_t base = ((size_t)win * 6 + h) * 49 * 32;
    for (int idx = t; idx < 49 * 32; idx += 256) {
        int r = idx >> 5, d = idx & 31;
        qs[r][d] = q[base + idx];
        ks[r][d] = k[base + idx];
        vs[r][d] = v[base + idx];
    }
    if (t < 49) {
        int wslot = win & 63;
        int wh = wslot >> 3, wc = wslot & 7;
        int i = t / 7, j = t - i * 7;
        int pr = wh * 7 + i, pc = wc * 7 + j;
        int r0 = (pr < 49) ? 0 : ((pr < 53) ? 1 : 2);
        int c0 = (pc < 49) ? 0 : ((pc < 53) ? 1 : 2);
        rid[t] = r0 * 3 + c0;
    }
    __syncthreads();

    const float scale = 0.17677669529663687f;

    for (int r = warp; r < 49; r += 8) {
        int ri = r / 7, rj = r - ri * 7;
        int c0 = lane, c1 = lane + 32;
        float s0, s1 = -1e30f;
        {
            float acc = 0.f;
            #pragma unroll
            for (int d = 0; d < 32; d++) acc += qs[r][d] * ks[c0][d];
            int ci = c0 / 7, cj = c0 - ci * 7;
            int bidx = (ri - ci + 6) * 13 + (rj - cj + 6);
            acc = acc * scale + bt[bidx * 6 + h];
            if (shift && rid[r] != rid[c0]) acc -= 100.f;
            s0 = acc;
        }
        if (c1 < 49) {
            float acc = 0.f;
            #pragma unroll
            for (int d = 0; d < 32; d++) acc += qs[r][d] * ks[c1][d];
            int ci = c1 / 7, cj = c1 - ci * 7;
            int bidx = (ri - ci + 6) * 13 + (rj - cj + 6);
            acc = acc * scale + bt[bidx * 6 + h];
            if (shift && rid[r] != rid[c1]) acc -= 100.f;
            s1 = acc;
        }
        float mx = fmaxf(s0, s1);
        #pragma unroll
        for (int o = 16; o; o >>= 1) mx = fmaxf(mx, __shfl_xor_sync(0xffffffffu, mx, o));
        float e0 = expf(s0 - mx);
        float e1 = (c1 < 49) ? expf(s1 - mx) : 0.f;
        float sum = e0 + e1;
        #pragma unroll
        for (int o = 16; o; o >>= 1) sum += __shfl_xor_sync(0xffffffffu, sum, o);
        prow[warp][c0] = e0;
        if (c1 < 49) prow[warp][c1] = e1;
        float inv = 1.f / sum;
        __syncwarp();
        float o = 0.f;
        #pragma unroll
        for (int c = 0; c < 49; c++) o += prow[warp][c] * vs[c][lane];
        o *= inv;
        out[((size_t)win * 49 + r) * 192 + h * 32 + lane] = f2tf32f(o);
        __syncwarp();
    }
}

// ---------------------------------------------------------------------------
extern "C" void kernel_launch(void* const* d_in, const int* in_sizes, int n_in,
                              void* d_out, int out_size)
{
    const float* x    = (const float*)d_in[0];
    const float* n1g  = (const float*)d_in[1];
    const float* n1b  = (const float*)d_in[2];
    const float* qkvw = (const float*)d_in[3];
    const float* qkvb = (const float*)d_in[4];
    const float* bt   = (const float*)d_in[5];
    const float* pw   = (const float*)d_in[6];
    const float* pb   = (const float*)d_in[7];
    const float* n2g  = (const float*)d_in[8];
    const float* n2b  = (const float*)d_in[9];
    const float* f1w  = (const float*)d_in[10];
    const float* f1b  = (const float*)d_in[11];
    const float* f2w  = (const float*)d_in[12];
    const float* f2b  = (const float*)d_in[13];
    float* xo = (float*)d_out;

    float *hw, *q, *k, *v, *h2, *wt;
    cudaGetSymbolAddress((void**)&hw, g_hw);
    cudaGetSymbolAddress((void**)&q,  g_q);
    cudaGetSymbolAddress((void**)&k,  g_k);
    cudaGetSymbolAddress((void**)&v,  g_v);
    cudaGetSymbolAddress((void**)&h2, g_h2);
    cudaGetSymbolAddress((void**)&wt, g_wt);

    cudaMemcpyAsync(xo, x, (size_t)TOKENS * 192 * sizeof(float),
                    cudaMemcpyDeviceToDevice, 0);

    // per-layer transposed weight offsets
    const size_t LSTR = 442368;
    for (int L = 0; L < 2; L++) {
        float* qkvT = wt + L * LSTR;
        float* projT = qkvT + 110592;
        float* fc1T = projT + 36864;
        float* fc2T = fc1T + 147456;
        transpose_tf32<<<dim3(6, 18),  dim3(32, 8)>>>(qkvw + (size_t)L * 110592, qkvT, 192, 576);
        transpose_tf32<<<dim3(6, 6),   dim3(32, 8)>>>(pw   + (size_t)L * 36864,  projT, 192, 192);
        transpose_tf32<<<dim3(6, 24),  dim3(32, 8)>>>(f1w  + (size_t)L * 147456, fc1T, 192, 768);
        transpose_tf32<<<dim3(24, 6),  dim3(32, 8)>>>(f2w  + (size_t)L * 147456, fc2T, 768, 192);
    }

    for (int L = 0; L < 2; L++) {
        int shift = (L & 1) ? 3 : 0;
        const float* qkvT = wt + L * LSTR;
        const float* projT = qkvT + 110592;
        const float* fc1T = projT + 36864;
        const float* fc2T = fc1T + 147456;

        ln_kernel<<<TOKENS, 192>>>(xo, n1g + L * 192, n1b + L * 192, hw, 1, shift);
        tc_gemm<0><<<dim3(9, 784), 256>>>(hw, qkvT, qkvb + L * 576, q, k, v, 192, 576, shift);
        attn_kernel<<<NWIN_TOT * 6, 256>>>(q, k, v, hw, bt + L * 169 * 6, shift);
        tc_gemm<1><<<dim3(3, 784), 256>>>(hw, projT, pb + L * 192, xo, 0, 0, 192, 192, shift);
        ln_kernel<<<TOKENS, 192>>>(xo, n2g + L * 192, n2b + L * 192, hw, 0, 0);
        tc_gemm<2><<<dim3(12, 784), 256>>>(hw, fc1T, f1b + L * 768, h2, 0, 0, 192, 768, 0);
        tc_gemm<3><<<dim3(3, 784), 256>>>(h2, fc2T, f2b + L * 192, xo, 0, 0, 768, 192, 0);
    }
}

// round 12
// speedup vs baseline: 2.2181x; 1.7392x over previous
#include <cuda_runtime.h>
#include <stdint.h>
#include <math.h>

// ---------------------------------------------------------------------------
// Swin block: B=32, H=W=56, C=192, NH=6, WS=7, N=49, NW=64/img, HD=32, DEPTH=2
// GEMMs: mma.sync m16n8k8 tf32 + ldmatrix + cp.async double buffering.
// BM=256, BN=64, BK=32; warp tile 64x32. LN is warp-per-token.
// ---------------------------------------------------------------------------
#define TOKENS 100352
#define NWIN_TOT 2048
#define QKV_ELEMS 19267584      // TOKENS*192

__device__ float g_hw[TOKENS * 192];
__device__ float g_q[QKV_ELEMS];
__device__ float g_k[QKV_ELEMS];
__device__ float g_v[QKV_ELEMS];
__device__ float g_h2[TOKENS * 768];
__device__ float g_wt[884736];   // transposed tf32 weights, layer stride 442368

__device__ __forceinline__ float f2tf32f(float f) {
    uint32_t r; asm("cvt.rna.tf32.f32 %0, %1;" : "=r"(r) : "f"(f));
    return __uint_as_float(r);
}

#define CP_ASYNC16(smem, gptr) \
    asm volatile("cp.async.cg.shared.global [%0], [%1], 16;" :: "r"(smem), "l"(gptr))
#define CP_COMMIT() asm volatile("cp.async.commit_group;" ::: "memory")
#define CP_WAIT0()  asm volatile("cp.async.wait_group 0;" ::: "memory")
#define CP_WAIT1()  asm volatile("cp.async.wait_group 1;" ::: "memory")

#define LDSM4(r0,r1,r2,r3,addr) \
    asm volatile("ldmatrix.sync.aligned.m8n8.x4.shared.b16 {%0,%1,%2,%3}, [%4];" \
        : "=r"(r0),"=r"(r1),"=r"(r2),"=r"(r3) : "r"(addr))

// ---------------------------------------------------------------------------
__global__ void transpose_tf32(const float* __restrict__ W, float* __restrict__ Wt,
                               int K, int N)
{
    __shared__ float tile[32][33];
    int k0 = blockIdx.x * 32, n0 = blockIdx.y * 32;
    int tx = threadIdx.x, ty = threadIdx.y;
    #pragma unroll
    for (int r = ty; r < 32; r += 8)
        tile[r][tx] = W[(size_t)(k0 + r) * N + n0 + tx];
    __syncthreads();
    #pragma unroll
    for (int r = ty; r < 32; r += 8)
        Wt[(size_t)(n0 + r) * K + k0 + tx] = f2tf32f(tile[tx][r]);
}

// ---------------------------------------------------------------------------
// tf32 tensor GEMM, BM=256 BN=64 BK=32, 256 threads = 8 warps (4m x 2n),
// warp tile 64x32 (4 mtiles x 4 ntiles = 16 MMA/kstep).
// Dynamic smem: 2 stages x (A 32KB + B 8KB) = 80KB.
// Epilogues: 0=QKV scatter, 1=proj+winrev+residual, 2=fc1+GELU, 3=fc2+residual
// ---------------------------------------------------------------------------
template <int EPI>
__global__ __launch_bounds__(256, 2)
void tc_gemm(const float* __restrict__ A, const float* __restrict__ Wt,
             const float* __restrict__ bias,
             float* __restrict__ O0, float* __restrict__ O1, float* __restrict__ O2,
             int K, int N, int shift)
{
    extern __shared__ __align__(128) float smem[];   // 2 * 10240 floats

    const int t    = threadIdx.x;
    const int lane = t & 31, warp = t >> 5;
    const int wm   = warp >> 1, wn = warp & 1;
    const int bm   = blockIdx.y * 256;
    const int bn   = blockIdx.x * 64;

    const uint32_t smb  = (uint32_t)__cvta_generic_to_shared(smem);
    const uint32_t xorv = (lane & 7) << 4;
    const int rowA = wm * 64 + (lane & 7) + ((lane >> 3) & 1) * 8;
    const uint32_t tA = ((lane >> 4) & 1) * 16;
    const int rowB = wn * 32 + (lane & 7);
    const uint32_t tB = (lane >> 3) * 16;

    float acc[4][4][4];
    #pragma unroll
    for (int i = 0; i < 4; i++)
        #pragma unroll
        for (int j = 0; j < 4; j++)
            #pragma unroll
            for (int e = 0; e < 4; e++) acc[i][j][e] = 0.f;

    auto issue_chunk = [&](int kc, int sel) {
        const int k0 = kc << 5;
        const uint32_t Ab = smb + sel * 40960;
        const uint32_t Bb = Ab + 32768;
        #pragma unroll
        for (int it = 0; it < 8; it++) {              // A: 2048 16B chunks
            int idx = t + it * 256;
            int row = idx >> 3, kq = idx & 7;
            uint32_t off = (uint32_t)(row * 128 + kq * 16) ^ ((row & 7) << 4);
            CP_ASYNC16(Ab + off, A + (size_t)(bm + row) * K + k0 + kq * 4);
        }
        #pragma unroll
        for (int it = 0; it < 2; it++) {              // B: 512 16B chunks
            int idx = t + it * 256;
            int n = idx >> 3, kq = idx & 7;
            uint32_t off = (uint32_t)(n * 128 + kq * 16) ^ ((n & 7) << 4);
            CP_ASYNC16(Bb + off, Wt + (size_t)(bn + n) * K + k0 + kq * 4);
        }
    };

    const int nch = K >> 5;
    issue_chunk(0, 0);
    CP_COMMIT();

    for (int kc = 0; kc < nch; kc++) {
        const int sel = kc & 1;
        if (kc + 1 < nch) {
            issue_chunk(kc + 1, sel ^ 1);
            CP_COMMIT();
            CP_WAIT1();
        } else {
            CP_WAIT0();
        }
        __syncthreads();

        const uint32_t Ab = smb + sel * 40960;
        const uint32_t Bb = Ab + 32768;

        #pragma unroll
        for (int ks2 = 0; ks2 < 2; ks2++) {
            uint32_t b[4][4];
            #pragma unroll
            for (int j = 0; j < 4; j++) {
                uint32_t addr = Bb + (((uint32_t)((rowB + j * 8) * 128) + ks2 * 64 + tB) ^ xorv);
                LDSM4(b[j][0], b[j][1], b[j][2], b[j][3], addr);
            }
            #pragma unroll
            for (int ki = 0; ki < 2; ki++) {
                const int ks = ks2 * 2 + ki;
                uint32_t a[4][4];
                #pragma unroll
                for (int i = 0; i < 4; i++) {
                    uint32_t addr = Ab + (((uint32_t)((rowA + i * 16) * 128) + ks * 32 + tA) ^ xorv);
                    LDSM4(a[i][0], a[i][1], a[i][2], a[i][3], addr);
                }
                #pragma unroll
                for (int i = 0; i < 4; i++)
                    #pragma unroll
                    for (int j = 0; j < 4; j++)
                        asm volatile(
                            "mma.sync.aligned.m16n8k8.row.col.f32.tf32.tf32.f32 "
                            "{%0,%1,%2,%3}, {%4,%5,%6,%7}, {%8,%9}, {%0,%1,%2,%3};"
                            : "+f"(acc[i][j][0]), "+f"(acc[i][j][1]),
                              "+f"(acc[i][j][2]), "+f"(acc[i][j][3])
                            : "r"(a[i][0]), "r"(a[i][1]), "r"(a[i][2]), "r"(a[i][3]),
                              "r"(b[j][ki * 2]), "r"(b[j][ki * 2 + 1]));
            }
        }
        __syncthreads();
    }

    // ---- epilogue ----------------------------------------------------------
    #pragma unroll
    for (int i = 0; i < 4; i++) {
        #pragma unroll
        for (int half = 0; half < 2; half++) {
            int m = bm + wm * 64 + i * 16 + (lane >> 2) + half * 8;
            int win = 0, n = 0;
            long dstTok = 0;
            if (EPI == 0 || EPI == 1) { win = m / 49; n = m - win * 49; }
            if (EPI == 1) {
                int bimg = win >> 6, wslot = win & 63;
                int wh = wslot >> 3, wc = wslot & 7;
                int ii = n / 7, jj = n - ii * 7;
                int dh = wh * 7 + ii + shift; if (dh >= 56) dh -= 56;
                int dw = wc * 7 + jj + shift; if (dw >= 56) dw -= 56;
                dstTok = (long)bimg * 3136 + dh * 56 + dw;
            }
            #pragma unroll
            for (int j = 0; j < 4; j++) {
                #pragma unroll
                for (int e = 0; e < 2; e++) {
                    int c = bn + wn * 32 + j * 8 + (lane & 3) * 2 + e;
                    float val = acc[i][j][half * 2 + e] + bias[c];
                    if (EPI == 0) {
                        int tsel = c / 192;
                        int rem  = c - tsel * 192;
                        int h = rem >> 5, d = rem & 31;
                        float* dst = (tsel == 0) ? O0 : ((tsel == 1) ? O1 : O2);
                        dst[(((size_t)win * 6 + h) * 49 + n) * 32 + d] = val;
                    } else if (EPI == 1) {
                        O0[(size_t)dstTok * 192 + c] += val;
                    } else if (EPI == 2) {
                        float g = 0.5f * val * (1.f + erff(val * 0.70710678118654752f));
                        O0[(size_t)m * N + c] = f2tf32f(g);
                    } else {
                        O0[(size_t)m * N + c] += val;
                    }
                }
            }
        }
    }
}

// ---------------------------------------------------------------------------
// LayerNorm, warp-per-token (8 tokens/CTA). Output rounded to tf32.
// ---------------------------------------------------------------------------
__global__ __launch_bounds__(256)
void ln_kernel(const float* __restrict__ x, const float* __restrict__ gam,
               const float* __restrict__ bet, float* __restrict__ out,
               int windowed, int shift)
{
    int t = threadIdx.x, warp = t >> 5, lane = t & 31;
    int m = blockIdx.x * 8 + warp;
    int src;
    if (windowed) {
        int win = m / 49, n = m - win * 49;
        int bimg = win >> 6, wslot = win & 63;
        int wh = wslot >> 3, wc = wslot & 7;
        int i = n / 7, j = n - i * 7;
        int sh = wh * 7 + i + shift; if (sh >= 56) sh -= 56;
        int sw = wc * 7 + j + shift; if (sw >= 56) sw -= 56;
        src = bimg * 3136 + sh * 56 + sw;
    } else {
        src = m;
    }
    const float4* xr = (const float4*)(x + (size_t)src * 192);
    float4 v0 = xr[lane];
    float4 v1 = make_float4(0.f, 0.f, 0.f, 0.f);
    if (lane < 16) v1 = xr[32 + lane];
    float s = v0.x + v0.y + v0.z + v0.w + v1.x + v1.y + v1.z + v1.w;
    float q = v0.x * v0.x + v0.y * v0.y + v0.z * v0.z + v0.w * v0.w
            + v1.x * v1.x + v1.y * v1.y + v1.z * v1.z + v1.w * v1.w;
    #pragma unroll
    for (int o = 16; o; o >>= 1) {
        s += __shfl_xor_sync(0xffffffffu, s, o);
        q += __shfl_xor_sync(0xffffffffu, q, o);
    }
    float mean = s * (1.f / 192.f);
    float var  = q * (1.f / 192.f) - mean * mean;
    float rstd = rsqrtf(var + 1e-5f);

    const float4* g4 = (const float4*)gam;
    const float4* b4 = (const float4*)bet;
    float4* o4 = (float4*)(out + (size_t)m * 192);
    {
        float4 g = g4[lane], b = b4[lane], r;
        r.x = f2tf32f((v0.x - mean) * rstd * g.x + b.x);
        r.y = f2tf32f((v0.y - mean) * rstd * g.y + b.y);
        r.z = f2tf32f((v0.z - mean) * rstd * g.z + b.z);
        r.w = f2tf32f((v0.w - mean) * rstd * g.w + b.w);
        o4[lane] = r;
    }
    if (lane < 16) {
        float4 g = g4[32 + lane], b = b4[32 + lane], r;
        r.x = f2tf32f((v1.x - mean) * rstd * g.x + b.x);
        r.y = f2tf32f((v1.y - mean) * rstd * g.y + b.y);
        r.z = f2tf32f((v1.z - mean) * rstd * g.z + b.z);
        r.w = f2tf32f((v1.w - mean) * rstd * g.w + b.w);
        o4[32 + lane] = r;
    }
}

// ---------------------------------------------------------------------------
// Attention: one block per (window, head). Output rounded to tf32 for proj.
// ---------------------------------------------------------------------------
__global__ __launch_bounds__(256)
void attn_kernel(const float* __restrict__ q, const float* __restrict__ k,
                 const float* __restrict__ v, float* __restrict__ out,
                 const float* __restrict__ bt, int shift)
{
    __shared__ float qs[49][33], ks[49][33], vs[49][33];
    __shared__ float prow[8][56];
    __shared__ int   rid[49];

    int blk  = blockIdx.x;
    int win  = blk / 6;
    int h    = blk - win * 6;
    int t    = threadIdx.x;
    int warp = t >> 5, lane = t & 31;

    size_t base = ((size_t)win * 6 + h) * 49 * 32;
    for (int idx = t; idx < 49 * 32; idx += 256) {
        int r = idx >> 5, d = idx & 31;
        qs[r][d] = q[base + idx];
        ks[r][d] = k[base + idx];
        vs[r][d] = v[base + idx];
    }
    if (t < 49) {
        int wslot = win & 63;
        int wh = wslot >> 3, wc = wslot & 7;
        int i = t / 7, j = t - i * 7;
        int pr = wh * 7 + i, pc = wc * 7 + j;
        int r0 = (pr < 49) ? 0 : ((pr < 53) ? 1 : 2);
        int c0 = (pc < 49) ? 0 : ((pc < 53) ? 1 : 2);
        rid[t] = r0 * 3 + c0;
    }
    __syncthreads();

    const float scale = 0.17677669529663687f;

    for (int r = warp; r < 49; r += 8) {
        int ri = r / 7, rj = r - ri * 7;
        int c0 = lane, c1 = lane + 32;
        float s0, s1 = -1e30f;
        {
            float acc = 0.f;
            #pragma unroll
            for (int d = 0; d < 32; d++) acc += qs[r][d] * ks[c0][d];
            int ci = c0 / 7, cj = c0 - ci * 7;
            int bidx = (ri - ci + 6) * 13 + (rj - cj + 6);
            acc = acc * scale + bt[bidx * 6 + h];
            if (shift && rid[r] != rid[c0]) acc -= 100.f;
            s0 = acc;
        }
        if (c1 < 49) {
            float acc = 0.f;
            #pragma unroll
            for (int d = 0; d < 32; d++) acc += qs[r][d] * ks[c1][d];
            int ci = c1 / 7, cj = c1 - ci * 7;
            int bidx = (ri - ci + 6) * 13 + (rj - cj + 6);
            acc = acc * scale + bt[bidx * 6 + h];
            if (shift && rid[r] != rid[c1]) acc -= 100.f;
            s1 = acc;
        }
        float mx = fmaxf(s0, s1);
        #pragma unroll
        for (int o = 16; o; o >>= 1) mx = fmaxf(mx, __shfl_xor_sync(0xffffffffu, mx, o));
        float e0 = expf(s0 - mx);
        float e1 = (c1 < 49) ? expf(s1 - mx) : 0.f;
        float sum = e0 + e1;
        #pragma unroll
        for (int o = 16; o; o >>= 1) sum += __shfl_xor_sync(0xffffffffu, sum, o);
        prow[warp][c0] = e0;
        if (c1 < 49) prow[warp][c1] = e1;
        float inv = 1.f / sum;
        __syncwarp();
        float o = 0.f;
        #pragma unroll
        for (int c = 0; c < 49; c++) o += prow[warp][c] * vs[c][lane];
        o *= inv;
        out[((size_t)win * 49 + r) * 192 + h * 32 + lane] = f2tf32f(o);
        __syncwarp();
    }
}

// ---------------------------------------------------------------------------
extern "C" void kernel_launch(void* const* d_in, const int* in_sizes, int n_in,
                              void* d_out, int out_size)
{
    const float* x    = (const float*)d_in[0];
    const float* n1g  = (const float*)d_in[1];
    const float* n1b  = (const float*)d_in[2];
    const float* qkvw = (const float*)d_in[3];
    const float* qkvb = (const float*)d_in[4];
    const float* bt   = (const float*)d_in[5];
    const float* pw   = (const float*)d_in[6];
    const float* pb   = (const float*)d_in[7];
    const float* n2g  = (const float*)d_in[8];
    const float* n2b  = (const float*)d_in[9];
    const float* f1w  = (const float*)d_in[10];
    const float* f1b  = (const float*)d_in[11];
    const float* f2w  = (const float*)d_in[12];
    const float* f2b  = (const float*)d_in[13];
    float* xo = (float*)d_out;

    float *hw, *q, *k, *v, *h2, *wt;
    cudaGetSymbolAddress((void**)&hw, g_hw);
    cudaGetSymbolAddress((void**)&q,  g_q);
    cudaGetSymbolAddress((void**)&k,  g_k);
    cudaGetSymbolAddress((void**)&v,  g_v);
    cudaGetSymbolAddress((void**)&h2, g_h2);
    cudaGetSymbolAddress((void**)&wt, g_wt);

    const int SMEM = 81920;
    cudaFuncSetAttribute(tc_gemm<0>, cudaFuncAttributeMaxDynamicSharedMemorySize, SMEM);
    cudaFuncSetAttribute(tc_gemm<1>, cudaFuncAttributeMaxDynamicSharedMemorySize, SMEM);
    cudaFuncSetAttribute(tc_gemm<2>, cudaFuncAttributeMaxDynamicSharedMemorySize, SMEM);
    cudaFuncSetAttribute(tc_gemm<3>, cudaFuncAttributeMaxDynamicSharedMemorySize, SMEM);

    cudaMemcpyAsync(xo, x, (size_t)TOKENS * 192 * sizeof(float),
                    cudaMemcpyDeviceToDevice, 0);

    const size_t LSTR = 442368;
    for (int L = 0; L < 2; L++) {
        float* qkvT = wt + L * LSTR;
        float* projT = qkvT + 110592;
        float* fc1T = projT + 36864;
        float* fc2T = fc1T + 147456;
        transpose_tf32<<<dim3(6, 18), dim3(32, 8)>>>(qkvw + (size_t)L * 110592, qkvT, 192, 576);
        transpose_tf32<<<dim3(6, 6),  dim3(32, 8)>>>(pw   + (size_t)L * 36864,  projT, 192, 192);
        transpose_tf32<<<dim3(6, 24), dim3(32, 8)>>>(f1w  + (size_t)L * 147456, fc1T, 192, 768);
        transpose_tf32<<<dim3(24, 6), dim3(32, 8)>>>(f2w  + (size_t)L * 147456, fc2T, 768, 192);
    }

    for (int L = 0; L < 2; L++) {
        int shift = (L & 1) ? 3 : 0;
        const float* qkvT = wt + L * LSTR;
        const float* projT = qkvT + 110592;
        const float* fc1T = projT + 36864;
        const float* fc2T = fc1T + 147456;

        ln_kernel<<<TOKENS / 8, 256>>>(xo, n1g + L * 192, n1b + L * 192, hw, 1, shift);
        tc_gemm<0><<<dim3(9, 392), 256, SMEM>>>(hw, qkvT, qkvb + L * 576, q, k, v, 192, 576, shift);
        attn_kernel<<<NWIN_TOT * 6, 256>>>(q, k, v, hw, bt + L * 169 * 6, shift);
        tc_gemm<1><<<dim3(3, 392), 256, SMEM>>>(hw, projT, pb + L * 192, xo, 0, 0, 192, 192, shift);
        ln_kernel<<<TOKENS / 8, 256>>>(xo, n2g + L * 192, n2b + L * 192, hw, 0, 0);
        tc_gemm<2><<<dim3(12, 392), 256, SMEM>>>(hw, fc1T, f1b + L * 768, h2, 0, 0, 192, 768, 0);
        tc_gemm<3><<<dim3(3, 392), 256, SMEM>>>(h2, fc2T, f2b + L * 192, xo, 0, 0, 768, 192, 0);
    }
}

// round 16
// speedup vs baseline: 2.5259x; 1.1388x over previous
#include <cuda_runtime.h>
#include <cuda_fp16.h>
#include <stdint.h>
#include <math.h>

// ---------------------------------------------------------------------------
// Swin block: B=32, H=W=56, C=192, NH=6, WS=7, N=49, NW=64/img, HD=32, DEPTH=2
// GEMMs: mma.sync m16n8k16 fp16 (fp32 accum) + ldmatrix + cp.async double buf.
// BM=256, BN=64, BK=64; warp tile 64x32. Activations/weights in half,
// residual stream + q/k/v + softmax in fp32.
// ---------------------------------------------------------------------------
#define TOKENS 100352
#define NWIN_TOT 2048
#define QKV_ELEMS 19267584      // TOKENS*192

__device__ __half g_hw[TOKENS * 192];
__device__ float  g_q[QKV_ELEMS];
__device__ float  g_k[QKV_ELEMS];
__device__ float  g_v[QKV_ELEMS];
__device__ __half g_h2[TOKENS * 768];
__device__ __half g_wt[884736];   // transposed fp16 weights, layer stride 442368

#define CP_ASYNC16(smem, gptr) \
    asm volatile("cp.async.cg.shared.global [%0], [%1], 16;" :: "r"(smem), "l"(gptr))
#define CP_COMMIT() asm volatile("cp.async.commit_group;" ::: "memory")
#define CP_WAIT0()  asm volatile("cp.async.wait_group 0;" ::: "memory")
#define CP_WAIT1()  asm volatile("cp.async.wait_group 1;" ::: "memory")

#define LDSM4(r0,r1,r2,r3,addr) \
    asm volatile("ldmatrix.sync.aligned.m8n8.x4.shared.b16 {%0,%1,%2,%3}, [%4];" \
        : "=r"(r0),"=r"(r1),"=r"(r2),"=r"(r3) : "r"(addr))

// ---------------------------------------------------------------------------
// Weight transpose + fp16: Wt[n*K+k] = half(W[k*N+n])
// ---------------------------------------------------------------------------
__global__ void transpose_f16(const float* __restrict__ W, __half* __restrict__ Wt,
                              int K, int N)
{
    __shared__ float tile[32][33];
    int k0 = blockIdx.x * 32, n0 = blockIdx.y * 32;
    int tx = threadIdx.x, ty = threadIdx.y;
    #pragma unroll
    for (int r = ty; r < 32; r += 8)
        tile[r][tx] = W[(size_t)(k0 + r) * N + n0 + tx];
    __syncthreads();
    #pragma unroll
    for (int r = ty; r < 32; r += 8)
        Wt[(size_t)(n0 + r) * K + k0 + tx] = __float2half(tile[tx][r]);
}

// ---------------------------------------------------------------------------
// fp16 tensor GEMM, BM=256 BN=64 BK=64, 256 threads = 8 warps (4m x 2n),
// warp tile 64x32. Smem: 2 stages x (A 32KB + B 8KB) = 80KB.
// Epilogues: 0=QKV scatter(fp32), 1=proj+winrev+residual(fp32),
//            2=fc1+GELU(->half), 3=fc2+residual(fp32)
// ---------------------------------------------------------------------------
template <int EPI>
__global__ __launch_bounds__(256, 2)
void tc_gemm(const __half* __restrict__ A, const __half* __restrict__ Wt,
             const float* __restrict__ bias,
             float* __restrict__ O0, float* __restrict__ O1, float* __restrict__ O2,
             __half* __restrict__ Oh,
             int K, int N, int shift)
{
    extern __shared__ __align__(128) char smem[];

    const int t    = threadIdx.x;
    const int lane = t & 31, warp = t >> 5;
    const int wm   = warp >> 1, wn = warp & 1;
    const int bm   = blockIdx.y * 256;
    const int bn   = blockIdx.x * 64;

    const uint32_t smb  = (uint32_t)__cvta_generic_to_shared(smem);
    const uint32_t xorv = (lane & 7) << 4;
    const int rowA = wm * 64 + (lane & 7) + ((lane >> 3) & 1) * 8;
    const uint32_t tA = ((lane >> 4) & 1) * 16;
    const int rowB = wn * 32 + (lane & 7) + ((lane >> 4) & 1) * 8;
    const uint32_t tB = ((lane >> 3) & 1) * 16;

    float acc[4][4][4];
    #pragma unroll
    for (int i = 0; i < 4; i++)
        #pragma unroll
        for (int j = 0; j < 4; j++)
            #pragma unroll
            for (int e = 0; e < 4; e++) acc[i][j][e] = 0.f;

    auto issue_chunk = [&](int kc, int sel) {
        const int k0 = kc << 6;                       // halves
        const uint32_t Ab = smb + sel * 40960;
        const uint32_t Bb = Ab + 32768;
        #pragma unroll
        for (int it = 0; it < 8; it++) {              // A: 2048 16B chunks
            int idx = t + it * 256;
            int row = idx >> 3, kq = idx & 7;
            uint32_t off = (uint32_t)(row * 128 + kq * 16) ^ ((row & 7) << 4);
            CP_ASYNC16(Ab + off, A + (size_t)(bm + row) * K + k0 + kq * 8);
        }
        #pragma unroll
        for (int it = 0; it < 2; it++) {              // B: 512 16B chunks
            int idx = t + it * 256;
            int n = idx >> 3, kq = idx & 7;
            uint32_t off = (uint32_t)(n * 128 + kq * 16) ^ ((n & 7) << 4);
            CP_ASYNC16(Bb + off, Wt + (size_t)(bn + n) * K + k0 + kq * 8);
        }
    };

    const int nch = K >> 6;
    issue_chunk(0, 0);
    CP_COMMIT();

    for (int kc = 0; kc < nch; kc++) {
        const int sel = kc & 1;
        if (kc + 1 < nch) {
            issue_chunk(kc + 1, sel ^ 1);
            CP_COMMIT();
            CP_WAIT1();
        } else {
            CP_WAIT0();
        }
        __syncthreads();

        const uint32_t Ab = smb + sel * 40960;
        const uint32_t Bb = Ab + 32768;

        #pragma unroll
        for (int ks = 0; ks < 4; ks++) {              // 4 k16 steps per chunk
            uint32_t b[8];
            #pragma unroll
            for (int jp = 0; jp < 2; jp++) {
                uint32_t addr = Bb +
                    (((uint32_t)((rowB + jp * 16) * 128) + ks * 32 + tB) ^ xorv);
                LDSM4(b[jp * 4 + 0], b[jp * 4 + 1], b[jp * 4 + 2], b[jp * 4 + 3], addr);
            }
            #pragma unroll
            for (int i = 0; i < 4; i++) {
                uint32_t a0, a1, a2, a3;
                uint32_t addr = Ab +
                    (((uint32_t)((rowA + i * 16) * 128) + ks * 32 + tA) ^ xorv);
                LDSM4(a0, a1, a2, a3, addr);
                #pragma unroll
                for (int j = 0; j < 4; j++)
                    asm volatile(
                        "mma.sync.aligned.m16n8k16.row.col.f32.f16.f16.f32 "
                        "{%0,%1,%2,%3}, {%4,%5,%6,%7}, {%8,%9}, {%0,%1,%2,%3};"
                        : "+f"(acc[i][j][0]), "+f"(acc[i][j][1]),
                          "+f"(acc[i][j][2]), "+f"(acc[i][j][3])
                        : "r"(a0), "r"(a1), "r"(a2), "r"(a3),
                          "r"(b[j * 2]), "r"(b[j * 2 + 1]));
            }
        }
        __syncthreads();
    }

    // ---- epilogue ----------------------------------------------------------
    #pragma unroll
    for (int i = 0; i < 4; i++) {
        #pragma unroll
        for (int half = 0; half < 2; half++) {
            int m = bm + wm * 64 + i * 16 + (lane >> 2) + half * 8;
            int win = 0, n = 0;
            long dstTok = 0;
            if (EPI == 0 || EPI == 1) { win = m / 49; n = m - win * 49; }
            if (EPI == 1) {
                int bimg = win >> 6, wslot = win & 63;
                int wh = wslot >> 3, wc = wslot & 7;
                int ii = n / 7, jj = n - ii * 7;
                int dh = wh * 7 + ii + shift; if (dh >= 56) dh -= 56;
                int dw = wc * 7 + jj + shift; if (dw >= 56) dw -= 56;
                dstTok = (long)bimg * 3136 + dh * 56 + dw;
            }
            #pragma unroll
            for (int j = 0; j < 4; j++) {
                #pragma unroll
                for (int e = 0; e < 2; e++) {
                    int c = bn + wn * 32 + j * 8 + (lane & 3) * 2 + e;
                    float val = acc[i][j][half * 2 + e] + bias[c];
                    if (EPI == 0) {
                        int tsel = c / 192;
                        int rem  = c - tsel * 192;
                        int h = rem >> 5, d = rem & 31;
                        float* dst = (tsel == 0) ? O0 : ((tsel == 1) ? O1 : O2);
                        dst[(((size_t)win * 6 + h) * 49 + n) * 32 + d] = val;
                    } else if (EPI == 1) {
                        O0[(size_t)dstTok * 192 + c] += val;
                    } else if (EPI == 2) {
                        float g = 0.5f * val * (1.f + erff(val * 0.70710678118654752f));
                        Oh[(size_t)m * N + c] = __float2half(g);
                    } else {
                        O0[(size_t)m * N + c] += val;
                    }
                }
            }
        }
    }
}

// ---------------------------------------------------------------------------
// LayerNorm, warp-per-token (8 tokens/CTA). Output fp16.
// ---------------------------------------------------------------------------
__global__ __launch_bounds__(256)
void ln_kernel(const float* __restrict__ x, const float* __restrict__ gam,
               const float* __restrict__ bet, __half* __restrict__ out,
               int windowed, int shift)
{
    int t = threadIdx.x, warp = t >> 5, lane = t & 31;
    int m = blockIdx.x * 8 + warp;
    int src;
    if (windowed) {
        int win = m / 49, n = m - win * 49;
        int bimg = win >> 6, wslot = win & 63;
        int wh = wslot >> 3, wc = wslot & 7;
        int i = n / 7, j = n - i * 7;
        int sh = wh * 7 + i + shift; if (sh >= 56) sh -= 56;
        int sw = wc * 7 + j + shift; if (sw >= 56) sw -= 56;
        src = bimg * 3136 + sh * 56 + sw;
    } else {
        src = m;
    }
    const float4* xr = (const float4*)(x + (size_t)src * 192);
    float4 v0 = xr[lane];
    float4 v1 = make_float4(0.f, 0.f, 0.f, 0.f);
    if (lane < 16) v1 = xr[32 + lane];
    float s = v0.x + v0.y + v0.z + v0.w + v1.x + v1.y + v1.z + v1.w;
    float q = v0.x * v0.x + v0.y * v0.y + v0.z * v0.z + v0.w * v0.w
            + v1.x * v1.x + v1.y * v1.y + v1.z * v1.z + v1.w * v1.w;
    #pragma unroll
    for (int o = 16; o; o >>= 1) {
        s += __shfl_xor_sync(0xffffffffu, s, o);
        q += __shfl_xor_sync(0xffffffffu, q, o);
    }
    float mean = s * (1.f / 192.f);
    float var  = q * (1.f / 192.f) - mean * mean;
    float rstd = rsqrtf(var + 1e-5f);

    const float4* g4 = (const float4*)gam;
    const float4* b4 = (const float4*)bet;
    __half2* o2 = (__half2*)(out + (size_t)m * 192);
    {
        float4 g = g4[lane], b = b4[lane];
        o2[lane * 2]     = __floats2half2_rn((v0.x - mean) * rstd * g.x + b.x,
                                             (v0.y - mean) * rstd * g.y + b.y);
        o2[lane * 2 + 1] = __floats2half2_rn((v0.z - mean) * rstd * g.z + b.z,
                                             (v0.w - mean) * rstd * g.w + b.w);
    }
    if (lane < 16) {
        float4 g = g4[32 + lane], b = b4[32 + lane];
        o2[64 + lane * 2]     = __floats2half2_rn((v1.x - mean) * rstd * g.x + b.x,
                                                  (v1.y - mean) * rstd * g.y + b.y);
        o2[64 + lane * 2 + 1] = __floats2half2_rn((v1.z - mean) * rstd * g.z + b.z,
                                                  (v1.w - mean) * rstd * g.w + b.w);
    }
}

// ---------------------------------------------------------------------------
// Attention: one block per (window, head), fp32 math, fp16 output.
// ---------------------------------------------------------------------------
__global__ __launch_bounds__(256)
void attn_kernel(const float* __restrict__ q, const float* __restrict__ k,
                 const float* __restrict__ v, __half* __restrict__ out,
                 const float* __restrict__ bt, int shift)
{
    __shared__ float qs[49][33], ks[49][33], vs[49][33];
    __shared__ float prow[8][56];
    __shared__ int   rid[49];

    int blk  = blockIdx.x;
    int win  = blk / 6;
    int h    = blk - win * 6;
    int t    = threadIdx.x;
    int warp = t >> 5, lane = t & 31;

    size_t base = ((size_t)win * 6 + h) * 49 * 32;
    for (int idx = t; idx < 49 * 32; idx += 256) {
        int r = idx >> 5, d = idx & 31;
        qs[r][d] = q[base + idx];
        ks[r][d] = k[base + idx];
        vs[r][d] = v[base + idx];
    }
    if (t < 49) {
        int wslot = win & 63;
        int wh = wslot >> 3, wc = wslot & 7;
        int i = t / 7, j = t - i * 7;
        int pr = wh * 7 + i, pc = wc * 7 + j;
        int r0 = (pr < 49) ? 0 : ((pr < 53) ? 1 : 2);
        int c0 = (pc < 49) ? 0 : ((pc < 53) ? 1 : 2);
        rid[t] = r0 * 3 + c0;
    }
    __syncthreads();

    const float scale = 0.17677669529663687f;

    for (int r = warp; r < 49; r += 8) {
        int ri = r / 7, rj = r - ri * 7;
        int c0 = lane, c1 = lane + 32;
        float s0, s1 = -1e30f;
        {
            float acc = 0.f;
            #pragma unroll
            for (int d = 0; d < 32; d++) acc += qs[r][d] * ks[c0][d];
            int ci = c0 / 7, cj = c0 - ci * 7;
            int bidx = (ri - ci + 6) * 13 + (rj - cj + 6);
            acc = acc * scale + bt[bidx * 6 + h];
            if (shift && rid[r] != rid[c0]) acc -= 100.f;
            s0 = acc;
        }
        if (c1 < 49) {
            float acc = 0.f;
            #pragma unroll
            for (int d = 0; d < 32; d++) acc += qs[r][d] * ks[c1][d];
            int ci = c1 / 7, cj = c1 - ci * 7;
            int bidx = (ri - ci + 6) * 13 + (rj - cj + 6);
            acc = acc * scale + bt[bidx * 6 + h];
            if (shift && rid[r] != rid[c1]) acc -= 100.f;
            s1 = acc;
        }
        float mx = fmaxf(s0, s1);
        #pragma unroll
        for (int o = 16; o; o >>= 1) mx = fmaxf(mx, __shfl_xor_sync(0xffffffffu, mx, o));
        float e0 = expf(s0 - mx);
        float e1 = (c1 < 49) ? expf(s1 - mx) : 0.f;
        float sum = e0 + e1;
        #pragma unroll
        for (int o = 16; o; o >>= 1) sum += __shfl_xor_sync(0xffffffffu, sum, o);
        prow[warp][c0] = e0;
        if (c1 < 49) prow[warp][c1] = e1;
        float inv = 1.f / sum;
        __syncwarp();
        float o = 0.f;
        #pragma unroll
        for (int c = 0; c < 49; c++) o += prow[warp][c] * vs[c][lane];
        o *= inv;
        out[((size_t)win * 49 + r) * 192 + h * 32 + lane] = __float2half(o);
        __syncwarp();
    }
}

// ---------------------------------------------------------------------------
extern "C" void kernel_launch(void* const* d_in, const int* in_sizes, int n_in,
                              void* d_out, int out_size)
{
    const float* x    = (const float*)d_in[0];
    const float* n1g  = (const float*)d_in[1];
    const float* n1b  = (const float*)d_in[2];
    const float* qkvw = (const float*)d_in[3];
    const float* qkvb = (const float*)d_in[4];
    const float* bt   = (const float*)d_in[5];
    const float* pw   = (const float*)d_in[6];
    const float* pb   = (const float*)d_in[7];
    const float* n2g  = (const float*)d_in[8];
    const float* n2b  = (const float*)d_in[9];
    const float* f1w  = (const float*)d_in[10];
    const float* f1b  = (const float*)d_in[11];
    const float* f2w  = (const float*)d_in[12];
    const float* f2b  = (const float*)d_in[13];
    float* xo = (float*)d_out;

    __half *hw, *h2, *wt;
    float *q, *k, *v;
    cudaGetSymbolAddress((void**)&hw, g_hw);
    cudaGetSymbolAddress((void**)&q,  g_q);
    cudaGetSymbolAddress((void**)&k,  g_k);
    cudaGetSymbolAddress((void**)&v,  g_v);
    cudaGetSymbolAddress((void**)&h2, g_h2);
    cudaGetSymbolAddress((void**)&wt, g_wt);

    const int SMEM = 81920;
    cudaFuncSetAttribute(tc_gemm<0>, cudaFuncAttributeMaxDynamicSharedMemorySize, SMEM);
    cudaFuncSetAttribute(tc_gemm<1>, cudaFuncAttributeMaxDynamicSharedMemorySize, SMEM);
    cudaFuncSetAttribute(tc_gemm<2>, cudaFuncAttributeMaxDynamicSharedMemorySize, SMEM);
    cudaFuncSetAttribute(tc_gemm<3>, cudaFuncAttributeMaxDynamicSharedMemorySize, SMEM);

    cudaMemcpyAsync(xo, x, (size_t)TOKENS * 192 * sizeof(float),
                    cudaMemcpyDeviceToDevice, 0);

    const size_t LSTR = 442368;
    for (int L = 0; L < 2; L++) {
        __half* qkvT = wt + L * LSTR;
        __half* projT = qkvT + 110592;
        __half* fc1T = projT + 36864;
        __half* fc2T = fc1T + 147456;
        transpose_f16<<<dim3(6, 18), dim3(32, 8)>>>(qkvw + (size_t)L * 110592, qkvT, 192, 576);
        transpose_f16<<<dim3(6, 6),  dim3(32, 8)>>>(pw   + (size_t)L * 36864,  projT, 192, 192);
        transpose_f16<<<dim3(6, 24), dim3(32, 8)>>>(f1w  + (size_t)L * 147456, fc1T, 192, 768);
        transpose_f16<<<dim3(24, 6), dim3(32, 8)>>>(f2w  + (size_t)L * 147456, fc2T, 768, 192);
    }

    for (int L = 0; L < 2; L++) {
        int shift = (L & 1) ? 3 : 0;
        const __half* qkvT = wt + L * LSTR;
        const __half* projT = qkvT + 110592;
        const __half* fc1T = projT + 36864;
        const __half* fc2T = fc1T + 147456;

        ln_kernel<<<TOKENS / 8, 256>>>(xo, n1g + L * 192, n1b + L * 192, hw, 1, shift);
        tc_gemm<0><<<dim3(9, 392), 256, SMEM>>>(hw, qkvT, qkvb + L * 576,
                                                q, k, v, 0, 192, 576, shift);
        attn_kernel<<<NWIN_TOT * 6, 256>>>(q, k, v, hw, bt + L * 169 * 6, shift);
        tc_gemm<1><<<dim3(3, 392), 256, SMEM>>>(hw, projT, pb + L * 192,
                                                xo, 0, 0, 0, 192, 192, shift);
        ln_kernel<<<TOKENS / 8, 256>>>(xo, n2g + L * 192, n2b + L * 192, hw, 0, 0);
        tc_gemm<2><<<dim3(12, 392), 256, SMEM>>>(hw, fc1T, f1b + L * 768,
                                                 0, 0, 0, h2, 192, 768, 0);
        tc_gemm<3><<<dim3(3, 392), 256, SMEM>>>(h2, fc2T, f2b + L * 192,
                                                xo, 0, 0, 0, 768, 192, 0);
    }
}

// round 17
// speedup vs baseline: 3.6809x; 1.4572x over previous
#include <cuda_runtime.h>
#include <cuda_fp16.h>
#include <stdint.h>
#include <math.h>

// ---------------------------------------------------------------------------
// Swin block: B=32, H=W=56, C=192, NH=6, WS=7, N=49, NW=64/img, HD=32, DEPTH=2
// GEMMs + attention on mma.sync m16n8k16 fp16 (fp32 accum). q/k/v fp16.
// ---------------------------------------------------------------------------
#define TOKENS 100352
#define NWIN_TOT 2048
#define QKV_ELEMS 19267584      // TOKENS*192

__device__ __half g_hw[TOKENS * 192];
__device__ __half g_q[QKV_ELEMS];
__device__ __half g_k[QKV_ELEMS];
__device__ __half g_v[QKV_ELEMS];
__device__ __half g_h2[TOKENS * 768];
__device__ __half g_wt[884736];   // transposed fp16 weights, layer stride 442368

#define CP_ASYNC16(smem, gptr) \
    asm volatile("cp.async.cg.shared.global [%0], [%1], 16;" :: "r"(smem), "l"(gptr))
#define CP_COMMIT() asm volatile("cp.async.commit_group;" ::: "memory")
#define CP_WAIT0()  asm volatile("cp.async.wait_group 0;" ::: "memory")
#define CP_WAIT1()  asm volatile("cp.async.wait_group 1;" ::: "memory")

#define LDSM4(r0,r1,r2,r3,addr) \
    asm volatile("ldmatrix.sync.aligned.m8n8.x4.shared.b16 {%0,%1,%2,%3}, [%4];" \
        : "=r"(r0),"=r"(r1),"=r"(r2),"=r"(r3) : "r"(addr))

#define MMA16816(d, a0,a1,a2,a3, b0,b1) \
    asm volatile("mma.sync.aligned.m16n8k16.row.col.f32.f16.f16.f32 " \
        "{%0,%1,%2,%3}, {%4,%5,%6,%7}, {%8,%9}, {%0,%1,%2,%3};" \
        : "+f"((d)[0]), "+f"((d)[1]), "+f"((d)[2]), "+f"((d)[3]) \
        : "r"(a0), "r"(a1), "r"(a2), "r"(a3), "r"(b0), "r"(b1))

// ---------------------------------------------------------------------------
// Batched weight transpose + fp16: one launch for all 8 matrices.
// ---------------------------------------------------------------------------
__global__ void transpose_all(const float* __restrict__ qkvw, const float* __restrict__ pw,
                              const float* __restrict__ f1w, const float* __restrict__ f2w,
                              __half* __restrict__ wt)
{
    __shared__ float tile[32][33];
    int job = blockIdx.z;          // 8 jobs: 2 layers x {qkv, proj, fc1, fc2}
    int L = job >> 2, m = job & 3;
    const float* W; __half* Wt; int K, N;
    __half* base = wt + (size_t)L * 442368;
    if (m == 0)      { W = qkvw + (size_t)L * 110592; Wt = base;                   K = 192; N = 576; }
    else if (m == 1) { W = pw   + (size_t)L * 36864;  Wt = base + 110592;          K = 192; N = 192; }
    else if (m == 2) { W = f1w  + (size_t)L * 147456; Wt = base + 110592 + 36864;  K = 192; N = 768; }
    else             { W = f2w  + (size_t)L * 147456; Wt = base + 110592 + 36864 + 147456; K = 768; N = 192; }
    int k0 = blockIdx.x * 32, n0 = blockIdx.y * 32;
    if (k0 >= K || n0 >= N) return;
    int tx = threadIdx.x, ty = threadIdx.y;
    #pragma unroll
    for (int r = ty; r < 32; r += 8)
        tile[r][tx] = W[(size_t)(k0 + r) * N + n0 + tx];
    __syncthreads();
    #pragma unroll
    for (int r = ty; r < 32; r += 8)
        Wt[(size_t)(n0 + r) * K + k0 + tx] = __float2half(tile[tx][r]);
}

// ---------------------------------------------------------------------------
// fp16 tensor GEMM, BM=256 BN=64 BK=64, 256 threads = 8 warps (4m x 2n),
// warp tile 64x32. Smem: 2 stages x (A 32KB + B 8KB) = 80KB.
// Epilogues: 0=QKV scatter(->half q/k/v), 1=proj+winrev+residual(fp32),
//            2=fc1+GELU(->half), 3=fc2+residual(fp32)
// ---------------------------------------------------------------------------
template <int EPI>
__global__ __launch_bounds__(256, 2)
void tc_gemm(const __half* __restrict__ A, const __half* __restrict__ Wt,
             const float* __restrict__ bias,
             float* __restrict__ O0,
             __half* __restrict__ Oh0, __half* __restrict__ Oh1, __half* __restrict__ Oh2,
             int K, int N, int shift)
{
    extern __shared__ __align__(128) char smem[];

    const int t    = threadIdx.x;
    const int lane = t & 31, warp = t >> 5;
    const int wm   = warp >> 1, wn = warp & 1;
    const int bm   = blockIdx.y * 256;
    const int bn   = blockIdx.x * 64;

    const uint32_t smb  = (uint32_t)__cvta_generic_to_shared(smem);
    const uint32_t xorv = (lane & 7) << 4;
    const int rowA = wm * 64 + (lane & 7) + ((lane >> 3) & 1) * 8;
    const uint32_t tA = ((lane >> 4) & 1) * 16;
    const int rowB = wn * 32 + (lane & 7) + ((lane >> 4) & 1) * 8;
    const uint32_t tB = ((lane >> 3) & 1) * 16;

    float acc[4][4][4];
    #pragma unroll
    for (int i = 0; i < 4; i++)
        #pragma unroll
        for (int j = 0; j < 4; j++)
            #pragma unroll
            for (int e = 0; e < 4; e++) acc[i][j][e] = 0.f;

    auto issue_chunk = [&](int kc, int sel) {
        const int k0 = kc << 6;
        const uint32_t Ab = smb + sel * 40960;
        const uint32_t Bb = Ab + 32768;
        #pragma unroll
        for (int it = 0; it < 8; it++) {
            int idx = t + it * 256;
            int row = idx >> 3, kq = idx & 7;
            uint32_t off = (uint32_t)(row * 128 + kq * 16) ^ ((row & 7) << 4);
            CP_ASYNC16(Ab + off, A + (size_t)(bm + row) * K + k0 + kq * 8);
        }
        #pragma unroll
        for (int it = 0; it < 2; it++) {
            int idx = t + it * 256;
            int n = idx >> 3, kq = idx & 7;
            uint32_t off = (uint32_t)(n * 128 + kq * 16) ^ ((n & 7) << 4);
            CP_ASYNC16(Bb + off, Wt + (size_t)(bn + n) * K + k0 + kq * 8);
        }
    };

    const int nch = K >> 6;
    issue_chunk(0, 0);
    CP_COMMIT();

    for (int kc = 0; kc < nch; kc++) {
        const int sel = kc & 1;
        if (kc + 1 < nch) {
            issue_chunk(kc + 1, sel ^ 1);
            CP_COMMIT();
            CP_WAIT1();
        } else {
            CP_WAIT0();
        }
        __syncthreads();

        const uint32_t Ab = smb + sel * 40960;
        const uint32_t Bb = Ab + 32768;

        #pragma unroll
        for (int ks = 0; ks < 4; ks++) {
            uint32_t b[8];
            #pragma unroll
            for (int jp = 0; jp < 2; jp++) {
                uint32_t addr = Bb +
                    (((uint32_t)((rowB + jp * 16) * 128) + ks * 32 + tB) ^ xorv);
                LDSM4(b[jp * 4 + 0], b[jp * 4 + 1], b[jp * 4 + 2], b[jp * 4 + 3], addr);
            }
            #pragma unroll
            for (int i = 0; i < 4; i++) {
                uint32_t a0, a1, a2, a3;
                uint32_t addr = Ab +
                    (((uint32_t)((rowA + i * 16) * 128) + ks * 32 + tA) ^ xorv);
                LDSM4(a0, a1, a2, a3, addr);
                #pragma unroll
                for (int j = 0; j < 4; j++)
                    MMA16816(acc[i][j], a0, a1, a2, a3, b[j * 2], b[j * 2 + 1]);
            }
        }
        __syncthreads();
    }

    #pragma unroll
    for (int i = 0; i < 4; i++) {
        #pragma unroll
        for (int half = 0; half < 2; half++) {
            int m = bm + wm * 64 + i * 16 + (lane >> 2) + half * 8;
            int win = 0, n = 0;
            long dstTok = 0;
            if (EPI == 0 || EPI == 1) { win = m / 49; n = m - win * 49; }
            if (EPI == 1) {
                int bimg = win >> 6, wslot = win & 63;
                int wh = wslot >> 3, wc = wslot & 7;
                int ii = n / 7, jj = n - ii * 7;
                int dh = wh * 7 + ii + shift; if (dh >= 56) dh -= 56;
                int dw = wc * 7 + jj + shift; if (dw >= 56) dw -= 56;
                dstTok = (long)bimg * 3136 + dh * 56 + dw;
            }
            #pragma unroll
            for (int j = 0; j < 4; j++) {
                #pragma unroll
                for (int e = 0; e < 2; e++) {
                    int c = bn + wn * 32 + j * 8 + (lane & 3) * 2 + e;
                    float val = acc[i][j][half * 2 + e] + bias[c];
                    if (EPI == 0) {
                        int tsel = c / 192;
                        int rem  = c - tsel * 192;
                        int h = rem >> 5, d = rem & 31;
                        __half* dst = (tsel == 0) ? Oh0 : ((tsel == 1) ? Oh1 : Oh2);
                        dst[(((size_t)win * 6 + h) * 49 + n) * 32 + d] = __float2half(val);
                    } else if (EPI == 1) {
                        O0[(size_t)dstTok * 192 + c] += val;
                    } else if (EPI == 2) {
                        float g = 0.5f * val * (1.f + erff(val * 0.70710678118654752f));
                        Oh0[(size_t)m * N + c] = __float2half(g);
                    } else {
                        O0[(size_t)m * N + c] += val;
                    }
                }
            }
        }
    }
}

// ---------------------------------------------------------------------------
// LayerNorm, warp-per-token (8 tokens/CTA). Output fp16.
// ---------------------------------------------------------------------------
__global__ __launch_bounds__(256)
void ln_kernel(const float* __restrict__ x, const float* __restrict__ gam,
               const float* __restrict__ bet, __half* __restrict__ out,
               int windowed, int shift)
{
    int t = threadIdx.x, warp = t >> 5, lane = t & 31;
    int m = blockIdx.x * 8 + warp;
    int src;
    if (windowed) {
        int win = m / 49, n = m - win * 49;
        int bimg = win >> 6, wslot = win & 63;
        int wh = wslot >> 3, wc = wslot & 7;
        int i = n / 7, j = n - i * 7;
        int sh = wh * 7 + i + shift; if (sh >= 56) sh -= 56;
        int sw = wc * 7 + j + shift; if (sw >= 56) sw -= 56;
        src = bimg * 3136 + sh * 56 + sw;
    } else {
        src = m;
    }
    const float4* xr = (const float4*)(x + (size_t)src * 192);
    float4 v0 = xr[lane];
    float4 v1 = make_float4(0.f, 0.f, 0.f, 0.f);
    if (lane < 16) v1 = xr[32 + lane];
    float s = v0.x + v0.y + v0.z + v0.w + v1.x + v1.y + v1.z + v1.w;
    float q = v0.x * v0.x + v0.y * v0.y + v0.z * v0.z + v0.w * v0.w
            + v1.x * v1.x + v1.y * v1.y + v1.z * v1.z + v1.w * v1.w;
    #pragma unroll
    for (int o = 16; o; o >>= 1) {
        s += __shfl_xor_sync(0xffffffffu, s, o);
        q += __shfl_xor_sync(0xffffffffu, q, o);
    }
    float mean = s * (1.f / 192.f);
    float var  = q * (1.f / 192.f) - mean * mean;
    float rstd = rsqrtf(var + 1e-5f);

    const float4* g4 = (const float4*)gam;
    const float4* b4 = (const float4*)bet;
    __half2* o2 = (__half2*)(out + (size_t)m * 192);
    {
        float4 g = g4[lane], b = b4[lane];
        o2[lane * 2]     = __floats2half2_rn((v0.x - mean) * rstd * g.x + b.x,
                                             (v0.y - mean) * rstd * g.y + b.y);
        o2[lane * 2 + 1] = __floats2half2_rn((v0.z - mean) * rstd * g.z + b.z,
                                             (v0.w - mean) * rstd * g.w + b.w);
    }
    if (lane < 16) {
        float4 g = g4[32 + lane], b = b4[32 + lane];
        o2[64 + lane * 2]     = __floats2half2_rn((v1.x - mean) * rstd * g.x + b.x,
                                                  (v1.y - mean) * rstd * g.y + b.y);
        o2[64 + lane * 2 + 1] = __floats2half2_rn((v1.z - mean) * rstd * g.z + b.z,
                                                  (v1.w - mean) * rstd * g.w + b.w);
    }
}

// ---------------------------------------------------------------------------
// Tensor-core attention: one 128-thread block per (window, head).
// Warp w handles m-rows [w*16, w*16+16). S = Q@K^T (8 ntiles, cols>=49
// masked), softmax in fragments, P->fp16, O = P@V^T, scaled by 1/rowsum.
// Smem geometry (128B rows + XOR swizzle) identical to the GEMM kernel.
// ---------------------------------------------------------------------------
__global__ __launch_bounds__(128)
void attn_mma(const __half* __restrict__ qg, const __half* __restrict__ kg,
              const __half* __restrict__ vg, __half* __restrict__ out,
              const float* __restrict__ bt, int shift)
{
    __shared__ __align__(128) __half Qs[64 * 64];
    __shared__ __align__(128) __half Ks[64 * 64];
    __shared__ __align__(128) __half Vt[32 * 64];
    __shared__ int rids[49];

    const int blk = blockIdx.x;
    const int win = blk / 6, h = blk - win * 6;
    const int t = threadIdx.x, lane = t & 31, mt = t >> 5;

    const uint32_t Qb = (uint32_t)__cvta_generic_to_shared(Qs);
    const uint32_t Kb = (uint32_t)__cvta_generic_to_shared(Ks);
    const uint32_t Vb = (uint32_t)__cvta_generic_to_shared(Vt);

    // zero V^T (token padding 49-63 must be 0 for the PV mma)
    for (int i = t; i < 256; i += 128) ((uint4*)Vt)[i] = make_uint4(0, 0, 0, 0);
    __syncthreads();

    const size_t base = ((size_t)win * 6 + h) * 1568;   // halves
    // Q, K: 49 rows x 32 halves, 16B-vector copies into swizzled 128B rows
    for (int i = t; i < 196; i += 128) {
        int row = i >> 2, cq = i & 3;
        uint32_t off = (uint32_t)(row * 128 + cq * 16) ^ ((row & 7) << 4);
        *(uint4*)((char*)Qs + off) = *(const uint4*)(qg + base + row * 32 + cq * 8);
        *(uint4*)((char*)Ks + off) = *(const uint4*)(kg + base + row * 32 + cq * 8);
    }
    // V transpose: Vt[d][token]
    for (int i = t; i < 1568; i += 128) {
        int tok = i >> 5, d = i & 31;
        uint32_t off = (uint32_t)(d * 128 + tok * 2) ^ ((d & 7) << 4);
        *(__half*)((char*)Vt + off) = vg[base + i];
    }
    if (t < 49) {
        int wslot = win & 63;
        int wh = wslot >> 3, wc = wslot & 7;
        int i = t / 7, j = t - i * 7;
        int pr = wh * 7 + i, pc = wc * 7 + j;
        int r0 = (pr < 49) ? 0 : ((pr < 53) ? 1 : 2);
        int c0 = (pc < 49) ? 0 : ((pc < 53) ? 1 : 2);
        rids[t] = r0 * 3 + c0;
    }
    __syncthreads();

    const uint32_t xorv = (lane & 7) << 4;
    const int rA = mt * 16 + (lane & 7) + ((lane >> 3) & 1) * 8;
    const uint32_t tAo = ((lane >> 4) & 1) * 16;
    const int rB = (lane & 7) + ((lane >> 4) & 1) * 8;
    const uint32_t tBo = ((lane >> 3) & 1) * 16;

    // ---- S = Q @ K^T -------------------------------------------------------
    float S[8][4];
    #pragma unroll
    for (int j = 0; j < 8; j++)
        #pragma unroll
        for (int e = 0; e < 4; e++) S[j][e] = 0.f;

    uint32_t aF[2][4];
    #pragma unroll
    for (int ks = 0; ks < 2; ks++) {
        uint32_t addr = Qb + (((uint32_t)(rA * 128) + ks * 32 + tAo) ^ xorv);
        LDSM4(aF[ks][0], aF[ks][1], aF[ks][2], aF[ks][3], addr);
    }
    #pragma unroll
    for (int jp = 0; jp < 4; jp++) {
        #pragma unroll
        for (int ks = 0; ks < 2; ks++) {
            uint32_t b0, b1, b2, b3;
            uint32_t addr = Kb + (((uint32_t)((rB + jp * 16) * 128) + ks * 32 + tBo) ^ xorv);
            LDSM4(b0, b1, b2, b3, addr);
            MMA16816(S[2 * jp],     aF[ks][0], aF[ks][1], aF[ks][2], aF[ks][3], b0, b1);
            MMA16816(S[2 * jp + 1], aF[ks][0], aF[ks][1], aF[ks][2], aF[ks][3], b2, b3);
        }
    }

    // ---- bias + mask -------------------------------------------------------
    const float scale = 0.17677669529663687f;   // 32^-0.5
    const int r0 = mt * 16 + (lane >> 2), r1 = r0 + 8;
    const int rr0 = (r0 < 49) ? r0 : 48, rr1 = (r1 < 49) ? r1 : 48;
    const int ri0 = rr0 / 7, rj0 = rr0 - ri0 * 7;
    const int ri1 = rr1 / 7, rj1 = rr1 - ri1 * 7;
    const int rid0 = rids[rr0], rid1 = rids[rr1];
    #pragma unroll
    for (int j = 0; j < 8; j++) {
        int cbase = j * 8 + (lane & 3) * 2;
        #pragma unroll
        for (int e = 0; e < 4; e++) {
            int c = cbase + (e & 1);
            if (c >= 49) { S[j][e] = -1e30f; continue; }
            int ci = c / 7, cj = c - ci * 7;
            int rc = rids[c];
            if (e < 2) {
                int bidx = (ri0 - ci + 6) * 13 + (rj0 - cj + 6);
                S[j][e] = S[j][e] * scale + bt[bidx * 6 + h];
                if (shift && rid0 != rc) S[j][e] -= 100.f;
            } else {
                int bidx = (ri1 - ci + 6) * 13 + (rj1 - cj + 6);
                S[j][e] = S[j][e] * scale + bt[bidx * 6 + h];
                if (shift && rid1 != rc) S[j][e] -= 100.f;
            }
        }
    }

    // ---- softmax (fragment-resident) --------------------------------------
    float mx0 = -1e30f, mx1 = -1e30f;
    #pragma unroll
    for (int j = 0; j < 8; j++) {
        mx0 = fmaxf(mx0, fmaxf(S[j][0], S[j][1]));
        mx1 = fmaxf(mx1, fmaxf(S[j][2], S[j][3]));
    }
    mx0 = fmaxf(mx0, __shfl_xor_sync(0xffffffffu, mx0, 1));
    mx0 = fmaxf(mx0, __shfl_xor_sync(0xffffffffu, mx0, 2));
    mx1 = fmaxf(mx1, __shfl_xor_sync(0xffffffffu, mx1, 1));
    mx1 = fmaxf(mx1, __shfl_xor_sync(0xffffffffu, mx1, 2));

    float s0 = 0.f, s1 = 0.f;
    uint32_t P[8][2];
    #pragma unroll
    for (int j = 0; j < 8; j++) {
        float e0 = expf(S[j][0] - mx0), e1 = expf(S[j][1] - mx0);
        float e2 = expf(S[j][2] - mx1), e3 = expf(S[j][3] - mx1);
        s0 += e0 + e1; s1 += e2 + e3;
        __half2 p0 = __floats2half2_rn(e0, e1);
        __half2 p1 = __floats2half2_rn(e2, e3);
        P[j][0] = *reinterpret_cast<uint32_t*>(&p0);
        P[j][1] = *reinterpret_cast<uint32_t*>(&p1);
    }
    s0 += __shfl_xor_sync(0xffffffffu, s0, 1);
    s0 += __shfl_xor_sync(0xffffffffu, s0, 2);
    s1 += __shfl_xor_sync(0xffffffffu, s1, 1);
    s1 += __shfl_xor_sync(0xffffffffu, s1, 2);
    float inv0 = 1.f / s0, inv1 = 1.f / s1;

    // ---- O = P @ V^T -------------------------------------------------------
    float O[4][4];
    #pragma unroll
    for (int j = 0; j < 4; j++)
        #pragma unroll
        for (int e = 0; e < 4; e++) O[j][e] = 0.f;

    #pragma unroll
    for (int ks = 0; ks < 4; ks++) {
        uint32_t a0 = P[2 * ks][0], a1 = P[2 * ks][1];
        uint32_t a2 = P[2 * ks + 1][0], a3 = P[2 * ks + 1][1];
        #pragma unroll
        for (int jp = 0; jp < 2; jp++) {
            uint32_t b0, b1, b2, b3;
            uint32_t addr = Vb + (((uint32_t)((rB + jp * 16) * 128) + ks * 32 + tBo) ^ xorv);
            LDSM4(b0, b1, b2, b3, addr);
            MMA16816(O[2 * jp],     a0, a1, a2, a3, b0, b1);
            MMA16816(O[2 * jp + 1], a0, a1, a2, a3, b2, b3);
        }
    }

    // ---- write (head-concatenated) ----------------------------------------
    size_t obase = (size_t)win * 49 * 192 + h * 32 + (lane & 3) * 2;
    if (r0 < 49) {
        #pragma unroll
        for (int j = 0; j < 4; j++) {
            __half2 hv = __floats2half2_rn(O[j][0] * inv0, O[j][1] * inv0);
            *(__half2*)(out + obase + (size_t)r0 * 192 + j * 8) = hv;
        }
    }
    if (r1 < 49) {
        #pragma unroll
        for (int j = 0; j < 4; j++) {
            __half2 hv = __floats2half2_rn(O[j][2] * inv1, O[j][3] * inv1);
            *(__half2*)(out + obase + (size_t)r1 * 192 + j * 8) = hv;
        }
    }
}

// ---------------------------------------------------------------------------
extern "C" void kernel_launch(void* const* d_in, const int* in_sizes, int n_in,
                              void* d_out, int out_size)
{
    const float* x    = (const float*)d_in[0];
    const float* n1g  = (const float*)d_in[1];
    const float* n1b  = (const float*)d_in[2];
    const float* qkvw = (const float*)d_in[3];
    const float* qkvb = (const float*)d_in[4];
    const float* bt   = (const float*)d_in[5];
    const float* pw   = (const float*)d_in[6];
    const float* pb   = (const float*)d_in[7];
    const float* n2g  = (const float*)d_in[8];
    const float* n2b  = (const float*)d_in[9];
    const float* f1w  = (const float*)d_in[10];
    const float* f1b  = (const float*)d_in[11];
    const float* f2w  = (const float*)d_in[12];
    const float* f2b  = (const float*)d_in[13];
    float* xo = (float*)d_out;

    __half *hw, *h2, *wt, *q, *k, *v;
    cudaGetSymbolAddress((void**)&hw, g_hw);
    cudaGetSymbolAddress((void**)&q,  g_q);
    cudaGetSymbolAddress((void**)&k,  g_k);
    cudaGetSymbolAddress((void**)&v,  g_v);
    cudaGetSymbolAddress((void**)&h2, g_h2);
    cudaGetSymbolAddress((void**)&wt, g_wt);

    const int SMEM = 81920;
    cudaFuncSetAttribute(tc_gemm<0>, cudaFuncAttributeMaxDynamicSharedMemorySize, SMEM);
    cudaFuncSetAttribute(tc_gemm<1>, cudaFuncAttributeMaxDynamicSharedMemorySize, SMEM);
    cudaFuncSetAttribute(tc_gemm<2>, cudaFuncAttributeMaxDynamicSharedMemorySize, SMEM);
    cudaFuncSetAttribute(tc_gemm<3>, cudaFuncAttributeMaxDynamicSharedMemorySize, SMEM);

    cudaMemcpyAsync(xo, x, (size_t)TOKENS * 192 * sizeof(float),
                    cudaMemcpyDeviceToDevice, 0);

    transpose_all<<<dim3(24, 24, 8), dim3(32, 8)>>>(qkvw, pw, f1w, f2w, wt);

    const size_t LSTR = 442368;
    for (int L = 0; L < 2; L++) {
        int shift = (L & 1) ? 3 : 0;
        const __half* qkvT = wt + L * LSTR;
        const __half* projT = qkvT + 110592;
        const __half* fc1T = projT + 36864;
        const __half* fc2T = fc1T + 147456;

        ln_kernel<<<TOKENS / 8, 256>>>(xo, n1g + L * 192, n1b + L * 192, hw, 1, shift);
        tc_gemm<0><<<dim3(9, 392), 256, SMEM>>>(hw, qkvT, qkvb + L * 576,
                                                0, q, k, v, 192, 576, shift);
        attn_mma<<<NWIN_TOT * 6, 128>>>(q, k, v, hw, bt + L * 169 * 6, shift);
        tc_gemm<1><<<dim3(3, 392), 256, SMEM>>>(hw, projT, pb + L * 192,
                                                xo, 0, 0, 0, 192, 192, shift);
        ln_kernel<<<TOKENS / 8, 256>>>(xo, n2g + L * 192, n2b + L * 192, hw, 0, 0);
        tc_gemm<2><<<dim3(12, 392), 256, SMEM>>>(hw, fc1T, f1b + L * 768,
                                                 0, h2, 0, 0, 192, 768, 0);
        tc_gemm<3><<<dim3(3, 392), 256, SMEM>>>(h2, fc2T, f2b + L * 192,
                                                xo, 0, 0, 0, 768, 192, 0);
    }
}